// round 6
// baseline (speedup 1.0000x reference)
#include <cuda_runtime.h>
#include <cuda_bf16.h>
#include <cstdint>
#include <math.h>

#define NN    50000
#define EE    800000
#define INDIM 300
#define HID   128
#define NL    4
#define LD    640        // (NL+1)*HID fp32 reps row
#define LD3   1920       // 3*LD  split-bf16 reps row
#define K3_X  960        // padded 3*300
#define K3_H  384        // 3*128
#define K3_F  1920       // 3*640

#define OFF_EMBW 0
#define OFF_LINL 122880
#define OFF_LINR 319488
#define OFF_FUS1 516096
#define OFF_FUS2 761856
#define W3_TOTAL 811008

#define DSMEM (1024 + 98304)

// ---------------- scratch ----------------
__device__ __align__(256) float          g_REPS [(size_t)NN * LD];
__device__ __align__(256) __nv_bfloat16  g_REPS3[(size_t)NN * LD3];
__device__ __align__(256) float          g_TMPF [(size_t)NN * HID];   // h@lin_r partial
__device__ __align__(256) __nv_bfloat16  g_X3   [(size_t)NN * K3_X];
__device__ __align__(256) __nv_bfloat16  g_AGG3 [(size_t)NN * K3_H];
__device__ __align__(256) __nv_bfloat16  g_TMP3 [(size_t)NN * K3_H];
__device__ __align__(256) __nv_bfloat16  g_W3   [W3_TOTAL];
__device__ float g_invdeg[NN];
__device__ int   g_cnt[NN];
__device__ int   g_cursor[NN];
__device__ int   g_rowptr[NN + 1];
__device__ int   g_col[EE];

// ---------------- helpers ----------------
__device__ __forceinline__ uint32_t smem_u32(const void* p) {
    uint32_t a;
    asm("{ .reg .u64 t; cvta.to.shared.u64 t, %1; cvt.u32.u64 %0, t; }" : "=r"(a) : "l"(p));
    return a;
}
#define SW128(b) ((b) ^ (((b) >> 3) & 0x70))

__device__ __forceinline__ void cp16(uint32_t dst, const void* src, int sz) {
    asm volatile("cp.async.cg.shared.global [%0], [%1], 16, %2;"
                 :: "r"(dst), "l"(src), "r"(sz) : "memory");
}
__device__ __forceinline__ void ldm_x4(uint32_t* r, uint32_t addr) {
    asm volatile("ldmatrix.sync.aligned.m8n8.x4.shared.b16 {%0,%1,%2,%3}, [%4];"
                 : "=r"(r[0]), "=r"(r[1]), "=r"(r[2]), "=r"(r[3]) : "r"(addr));
}
__device__ __forceinline__ void ldm_x2(uint32_t* r, uint32_t addr) {
    asm volatile("ldmatrix.sync.aligned.m8n8.x2.shared.b16 {%0,%1}, [%2];"
                 : "=r"(r[0]), "=r"(r[1]) : "r"(addr));
}
__device__ __forceinline__ void mma_bf16(float* c, const uint32_t* a, const uint32_t* b) {
    asm volatile(
        "mma.sync.aligned.m16n8k16.row.col.f32.bf16.bf16.f32 "
        "{%0,%1,%2,%3}, {%4,%5,%6,%7}, {%8,%9}, {%0,%1,%2,%3};"
        : "+f"(c[0]), "+f"(c[1]), "+f"(c[2]), "+f"(c[3])
        : "r"(a[0]), "r"(a[1]), "r"(a[2]), "r"(a[3]), "r"(b[0]), "r"(b[1]));
}
__device__ __forceinline__ void split2(float v, __nv_bfloat16& hi, __nv_bfloat16& lo) {
    hi = __float2bfloat16(v);
    lo = __float2bfloat16(v - __bfloat162float(hi));
}

// ---------------- CSR build ----------------
__global__ void k_count(const int* __restrict__ dst, int E) {
    int i = blockIdx.x * blockDim.x + threadIdx.x;
    if (i < E) atomicAdd(&g_cnt[dst[i]], 1);
}

__global__ void __launch_bounds__(1024) k_scan(int M) {
    const int T = 1024;
    int t = threadIdx.x;
    int per = (M + T - 1) / T;
    int beg = t * per;
    int end = min(beg + per, M);
    int sum = 0;
    for (int i = beg; i < end; i++) sum += g_cnt[i];

    int lane = t & 31, wid = t >> 5;
    int v = sum;
    #pragma unroll
    for (int o = 1; o < 32; o <<= 1) {
        int u = __shfl_up_sync(0xffffffffu, v, o);
        if (lane >= o) v += u;
    }
    __shared__ int ws[32];
    if (lane == 31) ws[wid] = v;
    __syncthreads();
    if (wid == 0) {
        int wv = ws[lane];
        #pragma unroll
        for (int o = 1; o < 32; o <<= 1) {
            int u = __shfl_up_sync(0xffffffffu, wv, o);
            if (lane >= o) wv += u;
        }
        ws[lane] = wv;
    }
    __syncthreads();
    int run = v - sum + (wid ? ws[wid - 1] : 0);
    for (int i = beg; i < end; i++) {
        int c = g_cnt[i];
        g_rowptr[i] = run;
        g_cursor[i] = run;
        g_invdeg[i] = 1.0f / fmaxf((float)c, 1.0f);
        run += c;
    }
    if (t == T - 1) g_rowptr[M] = run;
}

__global__ void k_fill(const int* __restrict__ src, const int* __restrict__ dst, int E) {
    int i = blockIdx.x * blockDim.x + threadIdx.x;
    if (i < E) {
        int pos = atomicAdd(&g_cursor[dst[i]], 1);
        g_col[pos] = src[i];
    }
}

// ---------------- weight prep (one launch) ----------------
__device__ __forceinline__ void wsplit_one(const float* W, __nv_bfloat16* o3,
                                           int idx, int K, int Kp) {
    int n = idx / Kp, kp = idx % Kp;
    __nv_bfloat16 hi, lo;
    if (kp < K) {
        split2(W[(size_t)kp * 128 + n], hi, lo);
    } else {
        hi = __float2bfloat16(0.f); lo = hi;
    }
    __nv_bfloat16* o = o3 + (size_t)n * (3 * Kp) + 3 * kp;
    o[0] = hi; o[1] = lo; o[2] = hi;
}

__global__ void k_wsplit_all(const float* __restrict__ emb_W,
                             const float* __restrict__ lin_l_W,
                             const float* __restrict__ lin_r_W,
                             const float* __restrict__ fus_W1,
                             const float* __restrict__ fus_W2) {
    int w = blockIdx.x * blockDim.x + threadIdx.x;
    if (w < 40960) {
        wsplit_one(emb_W, g_W3 + OFF_EMBW, w, 300, 320);
    } else if (w < 106496) {
        int u = w - 40960, i = u >> 14;
        wsplit_one(lin_l_W + (size_t)i * 16384, g_W3 + OFF_LINL + (size_t)i * 49152,
                   u & 16383, 128, 128);
    } else if (w < 172032) {
        int u = w - 106496, i = u >> 14;
        wsplit_one(lin_r_W + (size_t)i * 16384, g_W3 + OFF_LINR + (size_t)i * 49152,
                   u & 16383, 128, 128);
    } else if (w < 253952) {
        wsplit_one(fus_W1, g_W3 + OFF_FUS1, w - 172032, 640, 640);
    } else if (w < 270336) {
        wsplit_one(fus_W2, g_W3 + OFF_FUS2, w - 253952, 128, 128);
    }
}

__global__ void k_xsplit(const float* __restrict__ x, __nv_bfloat16* __restrict__ out, int M) {
    int idx = blockIdx.x * blockDim.x + threadIdx.x;
    int row = idx / 80, g = idx % 80;
    if (row >= M) return;
    float vv[4] = {0.f, 0.f, 0.f, 0.f};
    if (g < 75) {
        float4 t = *reinterpret_cast<const float4*>(x + (size_t)row * INDIM + g * 4);
        vv[0] = t.x; vv[1] = t.y; vv[2] = t.z; vv[3] = t.w;
    }
    union { __nv_bfloat16 h[12]; uint2 u[3]; } p;
    #pragma unroll
    for (int j = 0; j < 4; j++) {
        __nv_bfloat16 hi, lo; split2(vv[j], hi, lo);
        p.h[3 * j] = hi; p.h[3 * j + 1] = hi; p.h[3 * j + 2] = lo;
    }
    uint2* d = reinterpret_cast<uint2*>(out + (size_t)row * K3_X + g * 12);
    d[0] = p.u[0]; d[1] = p.u[1]; d[2] = p.u[2];
}

// ---------------- mean aggregation (fp32 gathers) -> split bf16 ----------------
__global__ void k_agg(const float* __restrict__ H /* REPS slice, ld=LD */,
                      __nv_bfloat16* __restrict__ out3, int M) {
    int gw   = (blockIdx.x * blockDim.x + threadIdx.x) >> 5;
    int lane = threadIdx.x & 31;
    if (gw >= M) return;
    int beg = g_rowptr[gw], end = g_rowptr[gw + 1];
    float a0 = 0.f, a1 = 0.f, a2 = 0.f, a3 = 0.f;
    float b0 = 0.f, b1 = 0.f, b2 = 0.f, b3 = 0.f;
    for (int base = beg; base < end; base += 32) {
        int idx = (base + lane < end) ? g_col[base + lane] : 0;
        int cnt = min(32, end - base);
        int j = 0;
        for (; j + 3 < cnt; j += 4) {
            int s0 = __shfl_sync(0xffffffffu, idx, j);
            int s1 = __shfl_sync(0xffffffffu, idx, j + 1);
            int s2 = __shfl_sync(0xffffffffu, idx, j + 2);
            int s3 = __shfl_sync(0xffffffffu, idx, j + 3);
            float4 v0 = *reinterpret_cast<const float4*>(H + (size_t)s0 * LD + lane * 4);
            float4 v1 = *reinterpret_cast<const float4*>(H + (size_t)s1 * LD + lane * 4);
            float4 v2 = *reinterpret_cast<const float4*>(H + (size_t)s2 * LD + lane * 4);
            float4 v3 = *reinterpret_cast<const float4*>(H + (size_t)s3 * LD + lane * 4);
            a0 += v0.x; a1 += v0.y; a2 += v0.z; a3 += v0.w;
            b0 += v1.x; b1 += v1.y; b2 += v1.z; b3 += v1.w;
            a0 += v2.x; a1 += v2.y; a2 += v2.z; a3 += v2.w;
            b0 += v3.x; b1 += v3.y; b2 += v3.z; b3 += v3.w;
        }
        for (; j < cnt; j++) {
            int s = __shfl_sync(0xffffffffu, idx, j);
            float4 v = *reinterpret_cast<const float4*>(H + (size_t)s * LD + lane * 4);
            a0 += v.x; a1 += v.y; a2 += v.z; a3 += v.w;
        }
    }
    a0 += b0; a1 += b1; a2 += b2; a3 += b3;
    float w = g_invdeg[gw];
    float m[4] = {a0 * w, a1 * w, a2 * w, a3 * w};
    union { __nv_bfloat16 h[12]; uint2 u[3]; } p;
    #pragma unroll
    for (int j = 0; j < 4; j++) {
        __nv_bfloat16 hi, lo; split2(m[j], hi, lo);
        p.h[3 * j] = hi; p.h[3 * j + 1] = hi; p.h[3 * j + 2] = lo;
    }
    uint2* d = reinterpret_cast<uint2*>(out3 + (size_t)gw * K3_H + lane * 12);
    d[0] = p.u[0]; d[1] = p.u[1]; d[2] = p.u[2];
}

// ---------------- tile loader ----------------
__device__ __forceinline__ void load_tiles(uint32_t tiles, int s, int tid, int m0, int M,
                                           const __nv_bfloat16* A, int lda,
                                           const __nv_bfloat16* B, int K, int k0) {
    uint32_t abase = tiles + (uint32_t)s * 32768u;
    uint32_t bbase = abase + 16384u;
    #pragma unroll
    for (int i = 0; i < 4; i++) {
        int v = tid + i * 256;
        int r = v >> 3, ch = v & 7;
        uint32_t bo = (uint32_t)(r * 128 + ch * 16);
        int row = m0 + r;
        int rc = row < M ? row : 0;
        const __nv_bfloat16* src = A + (size_t)rc * lda + k0 + ch * 8;
        cp16(abase + SW128(bo), src, row < M ? 16 : 0);
    }
    #pragma unroll
    for (int i = 0; i < 4; i++) {
        int v = tid + i * 256;
        int r = v >> 3, ch = v & 7;
        uint32_t bo = (uint32_t)(r * 128 + ch * 16);
        cp16(bbase + SW128(bo), B + (size_t)r * K + k0 + ch * 8, 16);
    }
    asm volatile("cp.async.commit_group;" ::: "memory");
}

// ---------------- mma.sync GEMM, 128x128 tile, BK=64, 3-stage ----------------
// MODE 0: C + bias                                  -> outF
// MODE 1: relu(C + bias)                            -> [outF] + split out3
// MODE 2: LN(C + addF + bias)*g+b (+skip), relu     -> [outF] + split out3
// MODE 3: C                                         -> outF (fp32, no bias)
template <int MODE>
__global__ void __launch_bounds__(256)
k_mgemm(const __nv_bfloat16* __restrict__ A0, int lda0, const __nv_bfloat16* __restrict__ B0, int K0,
        const __nv_bfloat16* __restrict__ A1, int lda1, const __nv_bfloat16* __restrict__ B1, int K1,
        const float* __restrict__ bias, const float* __restrict__ lng, const float* __restrict__ lnb,
        const float* __restrict__ skip, const float* __restrict__ addF,
        float* __restrict__ outF, int ldF,
        __nv_bfloat16* __restrict__ out3, int ld3, int M) {
    extern __shared__ char smem_raw[];
    char* smem = (char*)(((uintptr_t)smem_raw + 1023) & ~(uintptr_t)1023);
    const uint32_t tiles = smem_u32(smem);

    const int tid  = threadIdx.x;
    const int lane = tid & 31, wid = tid >> 5;
    const int m0   = blockIdx.x * 128;

    const int wm = (wid & 1) * 64;
    const int wn = (wid >> 1) * 32;

    float acc[4][4][4];
    #pragma unroll
    for (int i = 0; i < 4; i++)
        #pragma unroll
        for (int j = 0; j < 4; j++)
            #pragma unroll
            for (int q = 0; q < 4; q++) acc[i][j][q] = 0.f;

    const int nk0 = K0 / 64;
    const int nk  = nk0 + K1 / 64;

    const int r_in = ((lane >> 3) & 1) * 8 + (lane & 7);
    const int ca8  = (lane >> 4) * 8;
    const int rb   = lane & 7;
    const int cb8  = ((lane >> 3) & 1) * 8;

    auto load_chunk = [&](int cn, int s) {
        if (cn < nk0) load_tiles(tiles, s, tid, m0, M, A0, lda0, B0, K0, cn * 64);
        else          load_tiles(tiles, s, tid, m0, M, A1, lda1, B1, K1, (cn - nk0) * 64);
    };

    load_chunk(0, 0);
    if (nk > 1) load_chunk(1, 1);

    #pragma unroll 1
    for (int c = 0; c < nk; c++) {
        if (c + 1 < nk) asm volatile("cp.async.wait_group 1;" ::: "memory");
        else            asm volatile("cp.async.wait_group 0;" ::: "memory");
        __syncthreads();
        if (c + 2 < nk) load_chunk(c + 2, (c + 2) % 3);

        uint32_t abase = tiles + (uint32_t)(c % 3) * 32768u;
        uint32_t bbase = abase + 16384u;
        #pragma unroll
        for (int ka = 0; ka < 4; ka++) {
            uint32_t a[4][4];
            #pragma unroll
            for (int ma = 0; ma < 4; ma++) {
                int r = wm + ma * 16 + r_in, cc = ka * 16 + ca8;
                ldm_x4(a[ma], abase + SW128((uint32_t)(r * 128 + cc * 2)));
            }
            uint32_t b[4][2];
            #pragma unroll
            for (int na = 0; na < 4; na++) {
                int r = wn + na * 8 + rb, cc = ka * 16 + cb8;
                ldm_x2(b[na], bbase + SW128((uint32_t)(r * 128 + cc * 2)));
            }
            #pragma unroll
            for (int ma = 0; ma < 4; ma++)
                #pragma unroll
                for (int na = 0; na < 4; na++)
                    mma_bf16(acc[ma][na], a[ma], b[na]);
        }
    }
    __syncthreads();

    // park accumulators in smem C [128][132] fp32
    float* C = (float*)smem;
    #pragma unroll
    for (int ma = 0; ma < 4; ma++)
        #pragma unroll
        for (int na = 0; na < 4; na++) {
            int r0 = wm + ma * 16 + (lane >> 2);
            int cc = wn + na * 8 + 2 * (lane & 3);
            C[r0 * 132 + cc]           = acc[ma][na][0];
            C[r0 * 132 + cc + 1]       = acc[ma][na][1];
            C[(r0 + 8) * 132 + cc]     = acc[ma][na][2];
            C[(r0 + 8) * 132 + cc + 1] = acc[ma][na][3];
        }
    __syncthreads();

    // epilogue: warp per row
    #pragma unroll 1
    for (int t = 0; t < 16; t++) {
        int rr  = wid + t * 8;
        int row = m0 + rr;
        if (row >= M) continue;
        float4 v = *reinterpret_cast<float4*>(C + rr * 132 + lane * 4);
        if (MODE != 3) {
            float4 bb = *reinterpret_cast<const float4*>(bias + lane * 4);
            v.x += bb.x; v.y += bb.y; v.z += bb.z; v.w += bb.w;
        }
        if (MODE == 2) {
            float4 af = *reinterpret_cast<const float4*>(addF + (size_t)row * HID + lane * 4);
            v.x += af.x; v.y += af.y; v.z += af.z; v.w += af.w;
            float s  = v.x + v.y + v.z + v.w;
            float ss = v.x * v.x + v.y * v.y + v.z * v.z + v.w * v.w;
            #pragma unroll
            for (int off = 16; off; off >>= 1) {
                s  += __shfl_xor_sync(0xffffffffu, s,  off);
                ss += __shfl_xor_sync(0xffffffffu, ss, off);
            }
            float mu  = s * (1.0f / 128.0f);
            float var = ss * (1.0f / 128.0f) - mu * mu;
            float inv = rsqrtf(var + 1e-5f);
            float4 gg = *reinterpret_cast<const float4*>(lng + lane * 4);
            float4 ob = *reinterpret_cast<const float4*>(lnb + lane * 4);
            v.x = (v.x - mu) * inv * gg.x + ob.x;
            v.y = (v.y - mu) * inv * gg.y + ob.y;
            v.z = (v.z - mu) * inv * gg.z + ob.z;
            v.w = (v.w - mu) * inv * gg.w + ob.w;
            if (skip) {
                float4 sk = *reinterpret_cast<const float4*>(skip + (size_t)row * LD + lane * 4);
                v.x += sk.x; v.y += sk.y; v.z += sk.z; v.w += sk.w;
            }
        }
        if (MODE == 1 || MODE == 2) {
            v.x = fmaxf(v.x, 0.f); v.y = fmaxf(v.y, 0.f);
            v.z = fmaxf(v.z, 0.f); v.w = fmaxf(v.w, 0.f);
        }
        if (outF) {
            *reinterpret_cast<float4*>(outF + (size_t)row * ldF + lane * 4) = v;
        }
        if (MODE == 1 || MODE == 2) {
            union { __nv_bfloat16 h[12]; uint2 u[3]; } p;
            float vv[4] = {v.x, v.y, v.z, v.w};
            #pragma unroll
            for (int jj = 0; jj < 4; jj++) {
                __nv_bfloat16 hi, lo; split2(vv[jj], hi, lo);
                p.h[3 * jj] = hi; p.h[3 * jj + 1] = hi; p.h[3 * jj + 2] = lo;
            }
            uint2* d = reinterpret_cast<uint2*>(out3 + (size_t)row * ld3 + lane * 12);
            d[0] = p.u[0]; d[1] = p.u[1]; d[2] = p.u[2];
        }
    }
}

// ---------------- launch ----------------
extern "C" void kernel_launch(void* const* d_in, const int* in_sizes, int n_in,
                              void* d_out, int out_size) {
    const float* x       = (const float*)d_in[0];
    const int*   ei      = (const int*)  d_in[1];
    const float* emb_W   = (const float*)d_in[2];
    const float* emb_b   = (const float*)d_in[3];
    const float* lin_l_W = (const float*)d_in[4];
    const float* lin_l_b = (const float*)d_in[5];
    const float* lin_r_W = (const float*)d_in[6];
    const float* ln_g    = (const float*)d_in[7];
    const float* ln_b    = (const float*)d_in[8];
    const float* fus_W1  = (const float*)d_in[9];
    const float* fus_b1  = (const float*)d_in[10];
    const float* fus_W2  = (const float*)d_in[11];
    const float* fus_b2  = (const float*)d_in[12];
    float* out = (float*)d_out;

    const int M = in_sizes[0] / INDIM;
    const int E = in_sizes[1] / 2;

    float *REPS, *TMPF; __nv_bfloat16 *REPS3, *X3, *AGG3, *TMP3, *W3;
    int *CNT;
    cudaGetSymbolAddress((void**)&REPS,  g_REPS);
    cudaGetSymbolAddress((void**)&REPS3, g_REPS3);
    cudaGetSymbolAddress((void**)&TMPF,  g_TMPF);
    cudaGetSymbolAddress((void**)&X3,    g_X3);
    cudaGetSymbolAddress((void**)&AGG3,  g_AGG3);
    cudaGetSymbolAddress((void**)&TMP3,  g_TMP3);
    cudaGetSymbolAddress((void**)&W3,    g_W3);
    cudaGetSymbolAddress((void**)&CNT,   g_cnt);

    cudaFuncSetAttribute(k_mgemm<0>, cudaFuncAttributeMaxDynamicSharedMemorySize, DSMEM);
    cudaFuncSetAttribute(k_mgemm<1>, cudaFuncAttributeMaxDynamicSharedMemorySize, DSMEM);
    cudaFuncSetAttribute(k_mgemm<2>, cudaFuncAttributeMaxDynamicSharedMemorySize, DSMEM);
    cudaFuncSetAttribute(k_mgemm<3>, cudaFuncAttributeMaxDynamicSharedMemorySize, DSMEM);

    static cudaStream_t s1 = []() {
        cudaStream_t s; cudaStreamCreateWithFlags(&s, cudaStreamNonBlocking); return s;
    }();
    static cudaEvent_t evA = []() {
        cudaEvent_t e; cudaEventCreateWithFlags(&e, cudaEventDisableTiming); return e;
    }();
    static cudaEvent_t evB = []() {
        cudaEvent_t e; cudaEventCreateWithFlags(&e, cudaEventDisableTiming); return e;
    }();

    const int* src = ei;
    const int* dst = ei + E;

    const int G = (M + 127) / 128;
    const int warp_grid = (M + 7) / 8;

    // ---- prep + CSR, ordered so ncu -s 5 lands on the emb GEMM or scan ----
    cudaMemsetAsync(CNT, 0, (size_t)M * sizeof(int), 0);
    k_wsplit_all<<<(270336 + 255) / 256, 256>>>(emb_W, lin_l_W, lin_r_W, fus_W1, fus_W2);
    k_count<<<(E + 255) / 256, 256>>>(dst, E);
    k_xsplit<<<((M * 80) + 255) / 256, 256>>>(x, X3, M);
    // embedding: relu(x@W+b) -> REPS slice0 fp32 + REPS3 slice0 split
    k_mgemm<1><<<G, 256, DSMEM>>>(X3, K3_X, W3 + OFF_EMBW, K3_X,
                                  nullptr, 0, nullptr, 0,
                                  emb_b, nullptr, nullptr, nullptr, nullptr,
                                  REPS, LD, REPS3, LD3, M);
    k_scan<<<1, 1024>>>(M);
    k_fill<<<(E + 255) / 256, 256>>>(src, dst, E);

    // ---- layers: GEMM_r (side stream) overlaps k_agg (main) ----
    for (int i = 0; i < NL; i++) {
        cudaEventRecord(evA, 0);
        cudaStreamWaitEvent(s1, evA, 0);
        // h @ lin_r -> TMPF (fp32, no bias)   [tensor pipe]
        k_mgemm<3><<<G, 256, DSMEM, s1>>>(REPS3 + (size_t)i * K3_H, LD3,
                                          W3 + OFF_LINR + (size_t)i * 49152, K3_H,
                                          nullptr, 0, nullptr, 0,
                                          nullptr, nullptr, nullptr, nullptr, nullptr,
                                          TMPF, HID, nullptr, 0, M);
        cudaEventRecord(evB, s1);
        // mean aggregation                     [LSU/L2 pipe]
        k_agg<<<warp_grid, 256>>>(REPS + (size_t)i * HID, AGG3, M);
        cudaStreamWaitEvent(0, evB, 0);
        // agg @ lin_l + TMPF + b, LN, skip, relu
        k_mgemm<2><<<G, 256, DSMEM>>>(AGG3, K3_H, W3 + OFF_LINL + (size_t)i * 49152, K3_H,
                                      nullptr, 0, nullptr, 0,
                                      lin_l_b + (size_t)i * HID,
                                      ln_g + (size_t)i * HID, ln_b + (size_t)i * HID,
                                      (i > 0) ? (REPS + (size_t)i * HID) : nullptr, TMPF,
                                      (i + 1 < NL) ? (REPS + (size_t)(i + 1) * HID) : nullptr, LD,
                                      REPS3 + (size_t)(i + 1) * K3_H, LD3, M);
    }

    // ---- fusion MLP ----
    k_mgemm<1><<<G, 256, DSMEM>>>(REPS3, LD3, W3 + OFF_FUS1, K3_F,
                                  nullptr, 0, nullptr, 0,
                                  fus_b1, nullptr, nullptr, nullptr, nullptr,
                                  nullptr, 0, TMP3, K3_H, M);
    k_mgemm<0><<<G, 256, DSMEM>>>(TMP3, K3_H, W3 + OFF_FUS2, K3_H,
                                  nullptr, 0, nullptr, 0,
                                  fus_b2, nullptr, nullptr, nullptr, nullptr,
                                  out, HID, nullptr, 0, M);
}

// round 7
// speedup vs baseline: 1.0024x; 1.0024x over previous
#include <cuda_runtime.h>
#include <cuda_bf16.h>
#include <cstdint>
#include <math.h>

#define NN    50000
#define EE    800000
#define INDIM 300
#define HID   128
#define NL    4
#define LD    640        // (NL+1)*HID fp32 reps row
#define KX    320        // padded x width (bf16 hi/lo arrays)

// weight pack offsets (elements) — hi/lo arrays per matrix, [128][Kp] row-major
#define W_EMB_HI 0
#define W_EMB_LO 40960
#define W_LINL(i) (81920  + (i) * 32768)   // lo at +16384
#define W_LINR(i) (212992 + (i) * 32768)   // lo at +16384
#define W_FUS1_HI 344064
#define W_FUS1_LO 425984
#define W_FUS2_HI 507904
#define W_FUS2_LO 524288
#define W_TOTAL   540672

#define DSMEM (1024 + 98304)

// ---------------- scratch ----------------
__device__ __align__(256) float          g_REPS[(size_t)NN * LD];   // fp32 (agg gathers + skip)
__device__ __align__(256) __nv_bfloat16  g_RH  [(size_t)NN * LD];   // activation hi, ld 640
__device__ __align__(256) __nv_bfloat16  g_RL  [(size_t)NN * LD];   // activation lo, ld 640
__device__ __align__(256) __nv_bfloat16  g_XH  [(size_t)NN * KX];
__device__ __align__(256) __nv_bfloat16  g_XL  [(size_t)NN * KX];
__device__ __align__(256) __nv_bfloat16  g_AGGH[(size_t)NN * HID];
__device__ __align__(256) __nv_bfloat16  g_AGGL[(size_t)NN * HID];
__device__ __align__(256) __nv_bfloat16  g_TMPH[(size_t)NN * HID];
__device__ __align__(256) __nv_bfloat16  g_TMPL[(size_t)NN * HID];
__device__ __align__(256) __nv_bfloat16  g_W   [W_TOTAL];
__device__ float g_invdeg[NN];
__device__ int   g_cnt[NN];
__device__ int   g_cursor[NN];
__device__ int   g_rowptr[NN + 1];
__device__ int   g_col[EE];

// ---------------- segment descriptors ----------------
struct Seg { const __nv_bfloat16* A; const __nv_bfloat16* B; int lda; int ldb; int nch; };
struct SegList { Seg s[6]; int n; int nk; };

// ---------------- helpers ----------------
__device__ __forceinline__ uint32_t smem_u32(const void* p) {
    uint32_t a;
    asm("{ .reg .u64 t; cvta.to.shared.u64 t, %1; cvt.u32.u64 %0, t; }" : "=r"(a) : "l"(p));
    return a;
}
#define SW128(b) ((b) ^ (((b) >> 3) & 0x70))

__device__ __forceinline__ void cp16(uint32_t dst, const void* src, int sz) {
    asm volatile("cp.async.cg.shared.global [%0], [%1], 16, %2;"
                 :: "r"(dst), "l"(src), "r"(sz) : "memory");
}
__device__ __forceinline__ void ldm_x4(uint32_t* r, uint32_t addr) {
    asm volatile("ldmatrix.sync.aligned.m8n8.x4.shared.b16 {%0,%1,%2,%3}, [%4];"
                 : "=r"(r[0]), "=r"(r[1]), "=r"(r[2]), "=r"(r[3]) : "r"(addr));
}
__device__ __forceinline__ void ldm_x2(uint32_t* r, uint32_t addr) {
    asm volatile("ldmatrix.sync.aligned.m8n8.x2.shared.b16 {%0,%1}, [%2];"
                 : "=r"(r[0]), "=r"(r[1]) : "r"(addr));
}
__device__ __forceinline__ void mma_bf16(float* c, const uint32_t* a, const uint32_t* b) {
    asm volatile(
        "mma.sync.aligned.m16n8k16.row.col.f32.bf16.bf16.f32 "
        "{%0,%1,%2,%3}, {%4,%5,%6,%7}, {%8,%9}, {%0,%1,%2,%3};"
        : "+f"(c[0]), "+f"(c[1]), "+f"(c[2]), "+f"(c[3])
        : "r"(a[0]), "r"(a[1]), "r"(a[2]), "r"(a[3]), "r"(b[0]), "r"(b[1]));
}
__device__ __forceinline__ void split2(float v, __nv_bfloat16& hi, __nv_bfloat16& lo) {
    hi = __float2bfloat16(v);
    lo = __float2bfloat16(v - __bfloat162float(hi));
}

__device__ __forceinline__ void seg_lookup(const SegList& S, int c,
                                           const __nv_bfloat16*& A, int& lda,
                                           const __nv_bfloat16*& B, int& ldb, int& k0) {
    #pragma unroll
    for (int i = 0; i < 6; i++) {
        if (i < S.n) {
            if (c < S.s[i].nch) {
                A = S.s[i].A; lda = S.s[i].lda;
                B = S.s[i].B; ldb = S.s[i].ldb;
                k0 = c * 64;
                return;
            }
            c -= S.s[i].nch;
        }
    }
}

// ---------------- CSR build ----------------
__global__ void k_count(const int* __restrict__ dst, int E) {
    int i = blockIdx.x * blockDim.x + threadIdx.x;
    if (i < E) atomicAdd(&g_cnt[dst[i]], 1);
}

__global__ void __launch_bounds__(1024) k_scan(int M) {
    const int T = 1024;
    int t = threadIdx.x;
    int per = (M + T - 1) / T;
    int beg = t * per;
    int end = min(beg + per, M);
    int sum = 0;
    for (int i = beg; i < end; i++) sum += g_cnt[i];

    int lane = t & 31, wid = t >> 5;
    int v = sum;
    #pragma unroll
    for (int o = 1; o < 32; o <<= 1) {
        int u = __shfl_up_sync(0xffffffffu, v, o);
        if (lane >= o) v += u;
    }
    __shared__ int ws[32];
    if (lane == 31) ws[wid] = v;
    __syncthreads();
    if (wid == 0) {
        int wv = ws[lane];
        #pragma unroll
        for (int o = 1; o < 32; o <<= 1) {
            int u = __shfl_up_sync(0xffffffffu, wv, o);
            if (lane >= o) wv += u;
        }
        ws[lane] = wv;
    }
    __syncthreads();
    int run = v - sum + (wid ? ws[wid - 1] : 0);
    for (int i = beg; i < end; i++) {
        int c = g_cnt[i];
        g_rowptr[i] = run;
        g_cursor[i] = run;
        g_invdeg[i] = 1.0f / fmaxf((float)c, 1.0f);
        run += c;
    }
    if (t == T - 1) g_rowptr[M] = run;
}

__global__ void k_fill(const int* __restrict__ src, const int* __restrict__ dst, int E) {
    int i = blockIdx.x * blockDim.x + threadIdx.x;
    if (i < E) {
        int pos = atomicAdd(&g_cursor[dst[i]], 1);
        g_col[pos] = src[i];
    }
}

// ---------------- weight prep (one launch; writes hi+lo arrays) ----------------
__device__ __forceinline__ void wsplit_one(const float* W, __nv_bfloat16* ohi,
                                           __nv_bfloat16* olo, int idx, int K, int Kp) {
    int n = idx / Kp, kp = idx % Kp;
    __nv_bfloat16 hi, lo;
    if (kp < K) {
        split2(W[(size_t)kp * 128 + n], hi, lo);
    } else {
        hi = __float2bfloat16(0.f); lo = hi;
    }
    ohi[(size_t)n * Kp + kp] = hi;
    olo[(size_t)n * Kp + kp] = lo;
}

__global__ void k_wsplit_all(const float* __restrict__ emb_W,
                             const float* __restrict__ lin_l_W,
                             const float* __restrict__ lin_r_W,
                             const float* __restrict__ fus_W1,
                             const float* __restrict__ fus_W2) {
    int w = blockIdx.x * blockDim.x + threadIdx.x;
    if (w < 40960) {
        wsplit_one(emb_W, g_W + W_EMB_HI, g_W + W_EMB_LO, w, 300, 320);
    } else if (w < 106496) {
        int u = w - 40960, i = u >> 14;
        wsplit_one(lin_l_W + (size_t)i * 16384, g_W + W_LINL(i), g_W + W_LINL(i) + 16384,
                   u & 16383, 128, 128);
    } else if (w < 172032) {
        int u = w - 106496, i = u >> 14;
        wsplit_one(lin_r_W + (size_t)i * 16384, g_W + W_LINR(i), g_W + W_LINR(i) + 16384,
                   u & 16383, 128, 128);
    } else if (w < 253952) {
        wsplit_one(fus_W1, g_W + W_FUS1_HI, g_W + W_FUS1_LO, w - 172032, 640, 640);
    } else if (w < 270336) {
        wsplit_one(fus_W2, g_W + W_FUS2_HI, g_W + W_FUS2_LO, w - 253952, 128, 128);
    }
}

// x [M,300] fp32 -> XH/XL [M,320] bf16, zero pad
__global__ void k_xsplit(const float* __restrict__ x, int M) {
    int idx = blockIdx.x * blockDim.x + threadIdx.x;
    int row = idx / 80, g = idx % 80;
    if (row >= M) return;
    float vv[4] = {0.f, 0.f, 0.f, 0.f};
    if (g < 75) {
        float4 t = *reinterpret_cast<const float4*>(x + (size_t)row * INDIM + g * 4);
        vv[0] = t.x; vv[1] = t.y; vv[2] = t.z; vv[3] = t.w;
    }
    union { __nv_bfloat16 h[4]; uint2 u; } ph, pl;
    #pragma unroll
    for (int j = 0; j < 4; j++) split2(vv[j], ph.h[j], pl.h[j]);
    *reinterpret_cast<uint2*>(g_XH + (size_t)row * KX + g * 4) = ph.u;
    *reinterpret_cast<uint2*>(g_XL + (size_t)row * KX + g * 4) = pl.u;
}

// ---------------- mean aggregation (fp32 gathers) -> hi/lo bf16 ----------------
__global__ void k_agg(const float* __restrict__ H /* REPS slice, ld=LD */, int M) {
    int gw   = (blockIdx.x * blockDim.x + threadIdx.x) >> 5;
    int lane = threadIdx.x & 31;
    if (gw >= M) return;
    int beg = g_rowptr[gw], end = g_rowptr[gw + 1];
    float a0 = 0.f, a1 = 0.f, a2 = 0.f, a3 = 0.f;
    float b0 = 0.f, b1 = 0.f, b2 = 0.f, b3 = 0.f;
    for (int base = beg; base < end; base += 32) {
        int idx = (base + lane < end) ? g_col[base + lane] : 0;
        int cnt = min(32, end - base);
        int j = 0;
        for (; j + 3 < cnt; j += 4) {
            int s0 = __shfl_sync(0xffffffffu, idx, j);
            int s1 = __shfl_sync(0xffffffffu, idx, j + 1);
            int s2 = __shfl_sync(0xffffffffu, idx, j + 2);
            int s3 = __shfl_sync(0xffffffffu, idx, j + 3);
            float4 v0 = *reinterpret_cast<const float4*>(H + (size_t)s0 * LD + lane * 4);
            float4 v1 = *reinterpret_cast<const float4*>(H + (size_t)s1 * LD + lane * 4);
            float4 v2 = *reinterpret_cast<const float4*>(H + (size_t)s2 * LD + lane * 4);
            float4 v3 = *reinterpret_cast<const float4*>(H + (size_t)s3 * LD + lane * 4);
            a0 += v0.x; a1 += v0.y; a2 += v0.z; a3 += v0.w;
            b0 += v1.x; b1 += v1.y; b2 += v1.z; b3 += v1.w;
            a0 += v2.x; a1 += v2.y; a2 += v2.z; a3 += v2.w;
            b0 += v3.x; b1 += v3.y; b2 += v3.z; b3 += v3.w;
        }
        for (; j < cnt; j++) {
            int s = __shfl_sync(0xffffffffu, idx, j);
            float4 v = *reinterpret_cast<const float4*>(H + (size_t)s * LD + lane * 4);
            a0 += v.x; a1 += v.y; a2 += v.z; a3 += v.w;
        }
    }
    a0 += b0; a1 += b1; a2 += b2; a3 += b3;
    float w = g_invdeg[gw];
    float m[4] = {a0 * w, a1 * w, a2 * w, a3 * w};
    union { __nv_bfloat16 h[4]; uint2 u; } ph, pl;
    #pragma unroll
    for (int j = 0; j < 4; j++) split2(m[j], ph.h[j], pl.h[j]);
    *reinterpret_cast<uint2*>(g_AGGH + (size_t)gw * HID + lane * 4) = ph.u;
    *reinterpret_cast<uint2*>(g_AGGL + (size_t)gw * HID + lane * 4) = pl.u;
}

// ---------------- tile loader ----------------
__device__ __forceinline__ void load_tiles(uint32_t tiles, int s, int tid, int m0, int M,
                                           const __nv_bfloat16* A, int lda,
                                           const __nv_bfloat16* B, int ldb, int k0) {
    uint32_t abase = tiles + (uint32_t)s * 32768u;
    uint32_t bbase = abase + 16384u;
    #pragma unroll
    for (int i = 0; i < 4; i++) {
        int v = tid + i * 256;
        int r = v >> 3, ch = v & 7;
        uint32_t bo = (uint32_t)(r * 128 + ch * 16);
        int row = m0 + r;
        int rc = row < M ? row : 0;
        const __nv_bfloat16* src = A + (size_t)rc * lda + k0 + ch * 8;
        cp16(abase + SW128(bo), src, row < M ? 16 : 0);
    }
    #pragma unroll
    for (int i = 0; i < 4; i++) {
        int v = tid + i * 256;
        int r = v >> 3, ch = v & 7;
        uint32_t bo = (uint32_t)(r * 128 + ch * 16);
        cp16(bbase + SW128(bo), B + (size_t)r * ldb + k0 + ch * 8, 16);
    }
    asm volatile("cp.async.commit_group;" ::: "memory");
}

// ---------------- mma.sync GEMM, 128x128 tile, BK=64, 3-stage, segment list ----------------
// MODE 0: C + bias                              -> outF
// MODE 1: relu(C + bias)                        -> [outF] + (outH,outL)
// MODE 2: LN(C + bias)*g+b (+skip), relu        -> [outF] + (outH,outL)
template <int MODE>
__global__ void __launch_bounds__(256)
k_mgemm(SegList segs,
        const float* __restrict__ bias, const float* __restrict__ lng, const float* __restrict__ lnb,
        const float* __restrict__ skip, float* __restrict__ outF, int ldF,
        __nv_bfloat16* __restrict__ outH, __nv_bfloat16* __restrict__ outL, int ldo, int M) {
    extern __shared__ char smem_raw[];
    char* smem = (char*)(((uintptr_t)smem_raw + 1023) & ~(uintptr_t)1023);
    const uint32_t tiles = smem_u32(smem);

    const int tid  = threadIdx.x;
    const int lane = tid & 31, wid = tid >> 5;
    const int m0   = blockIdx.x * 128;

    const int wm = (wid & 1) * 64;
    const int wn = (wid >> 1) * 32;

    float acc[4][4][4];
    #pragma unroll
    for (int i = 0; i < 4; i++)
        #pragma unroll
        for (int j = 0; j < 4; j++)
            #pragma unroll
            for (int q = 0; q < 4; q++) acc[i][j][q] = 0.f;

    const int nk = segs.nk;

    const int r_in = ((lane >> 3) & 1) * 8 + (lane & 7);
    const int ca8  = (lane >> 4) * 8;
    const int rb   = lane & 7;
    const int cb8  = ((lane >> 3) & 1) * 8;

    auto load_chunk = [&](int cn, int s) {
        const __nv_bfloat16 *A, *B; int lda, ldb, k0;
        seg_lookup(segs, cn, A, lda, B, ldb, k0);
        load_tiles(tiles, s, tid, m0, M, A, lda, B, ldb, k0);
    };

    load_chunk(0, 0);
    if (nk > 1) load_chunk(1, 1);

    #pragma unroll 1
    for (int c = 0; c < nk; c++) {
        if (c + 1 < nk) asm volatile("cp.async.wait_group 1;" ::: "memory");
        else            asm volatile("cp.async.wait_group 0;" ::: "memory");
        __syncthreads();
        if (c + 2 < nk) load_chunk(c + 2, (c + 2) % 3);

        uint32_t abase = tiles + (uint32_t)(c % 3) * 32768u;
        uint32_t bbase = abase + 16384u;
        #pragma unroll
        for (int ka = 0; ka < 4; ka++) {
            uint32_t a[4][4];
            #pragma unroll
            for (int ma = 0; ma < 4; ma++) {
                int r = wm + ma * 16 + r_in, cc = ka * 16 + ca8;
                ldm_x4(a[ma], abase + SW128((uint32_t)(r * 128 + cc * 2)));
            }
            uint32_t b[4][2];
            #pragma unroll
            for (int na = 0; na < 4; na++) {
                int r = wn + na * 8 + rb, cc = ka * 16 + cb8;
                ldm_x2(b[na], bbase + SW128((uint32_t)(r * 128 + cc * 2)));
            }
            #pragma unroll
            for (int ma = 0; ma < 4; ma++)
                #pragma unroll
                for (int na = 0; na < 4; na++)
                    mma_bf16(acc[ma][na], a[ma], b[na]);
        }
    }
    __syncthreads();

    // park accumulators in smem C [128][132] fp32
    float* C = (float*)smem;
    #pragma unroll
    for (int ma = 0; ma < 4; ma++)
        #pragma unroll
        for (int na = 0; na < 4; na++) {
            int r0 = wm + ma * 16 + (lane >> 2);
            int cc = wn + na * 8 + 2 * (lane & 3);
            C[r0 * 132 + cc]           = acc[ma][na][0];
            C[r0 * 132 + cc + 1]       = acc[ma][na][1];
            C[(r0 + 8) * 132 + cc]     = acc[ma][na][2];
            C[(r0 + 8) * 132 + cc + 1] = acc[ma][na][3];
        }
    __syncthreads();

    // epilogue: warp per row
    #pragma unroll 1
    for (int t = 0; t < 16; t++) {
        int rr  = wid + t * 8;
        int row = m0 + rr;
        if (row >= M) continue;
        float4 v = *reinterpret_cast<float4*>(C + rr * 132 + lane * 4);
        float4 bb = *reinterpret_cast<const float4*>(bias + lane * 4);
        v.x += bb.x; v.y += bb.y; v.z += bb.z; v.w += bb.w;
        if (MODE == 2) {
            float s  = v.x + v.y + v.z + v.w;
            float ss = v.x * v.x + v.y * v.y + v.z * v.z + v.w * v.w;
            #pragma unroll
            for (int off = 16; off; off >>= 1) {
                s  += __shfl_xor_sync(0xffffffffu, s,  off);
                ss += __shfl_xor_sync(0xffffffffu, ss, off);
            }
            float mu  = s * (1.0f / 128.0f);
            float var = ss * (1.0f / 128.0f) - mu * mu;
            float inv = rsqrtf(var + 1e-5f);
            float4 gg = *reinterpret_cast<const float4*>(lng + lane * 4);
            float4 ob = *reinterpret_cast<const float4*>(lnb + lane * 4);
            v.x = (v.x - mu) * inv * gg.x + ob.x;
            v.y = (v.y - mu) * inv * gg.y + ob.y;
            v.z = (v.z - mu) * inv * gg.z + ob.z;
            v.w = (v.w - mu) * inv * gg.w + ob.w;
            if (skip) {
                float4 sk = *reinterpret_cast<const float4*>(skip + (size_t)row * LD + lane * 4);
                v.x += sk.x; v.y += sk.y; v.z += sk.z; v.w += sk.w;
            }
        }
        if (MODE != 0) {
            v.x = fmaxf(v.x, 0.f); v.y = fmaxf(v.y, 0.f);
            v.z = fmaxf(v.z, 0.f); v.w = fmaxf(v.w, 0.f);
        }
        if (outF) {
            *reinterpret_cast<float4*>(outF + (size_t)row * ldF + lane * 4) = v;
        }
        if (MODE != 0) {
            union { __nv_bfloat16 h[4]; uint2 u; } ph, pl;
            float vv[4] = {v.x, v.y, v.z, v.w};
            #pragma unroll
            for (int jj = 0; jj < 4; jj++) split2(vv[jj], ph.h[jj], pl.h[jj]);
            *reinterpret_cast<uint2*>(outH + (size_t)row * ldo + lane * 4) = ph.u;
            *reinterpret_cast<uint2*>(outL + (size_t)row * ldo + lane * 4) = pl.u;
        }
    }
}

// host-side seg builders
static inline Seg mkseg(const __nv_bfloat16* A, int lda, const __nv_bfloat16* B, int ldb, int nch) {
    Seg s; s.A = A; s.B = B; s.lda = lda; s.ldb = ldb; s.nch = nch; return s;
}

// ---------------- launch ----------------
extern "C" void kernel_launch(void* const* d_in, const int* in_sizes, int n_in,
                              void* d_out, int out_size) {
    const float* x       = (const float*)d_in[0];
    const int*   ei      = (const int*)  d_in[1];
    const float* emb_W   = (const float*)d_in[2];
    const float* emb_b   = (const float*)d_in[3];
    const float* lin_l_W = (const float*)d_in[4];
    const float* lin_l_b = (const float*)d_in[5];
    const float* lin_r_W = (const float*)d_in[6];
    const float* ln_g    = (const float*)d_in[7];
    const float* ln_b    = (const float*)d_in[8];
    const float* fus_W1  = (const float*)d_in[9];
    const float* fus_b1  = (const float*)d_in[10];
    const float* fus_W2  = (const float*)d_in[11];
    const float* fus_b2  = (const float*)d_in[12];
    float* out = (float*)d_out;

    const int M = in_sizes[0] / INDIM;
    const int E = in_sizes[1] / 2;

    float *REPS; __nv_bfloat16 *RH, *RL, *XH, *XL, *AGGH, *AGGL, *TMPH, *TMPL, *W;
    int *CNT;
    cudaGetSymbolAddress((void**)&REPS, g_REPS);
    cudaGetSymbolAddress((void**)&RH,   g_RH);
    cudaGetSymbolAddress((void**)&RL,   g_RL);
    cudaGetSymbolAddress((void**)&XH,   g_XH);
    cudaGetSymbolAddress((void**)&XL,   g_XL);
    cudaGetSymbolAddress((void**)&AGGH, g_AGGH);
    cudaGetSymbolAddress((void**)&AGGL, g_AGGL);
    cudaGetSymbolAddress((void**)&TMPH, g_TMPH);
    cudaGetSymbolAddress((void**)&TMPL, g_TMPL);
    cudaGetSymbolAddress((void**)&W,    g_W);
    cudaGetSymbolAddress((void**)&CNT,  g_cnt);

    cudaFuncSetAttribute(k_mgemm<0>, cudaFuncAttributeMaxDynamicSharedMemorySize, DSMEM);
    cudaFuncSetAttribute(k_mgemm<1>, cudaFuncAttributeMaxDynamicSharedMemorySize, DSMEM);
    cudaFuncSetAttribute(k_mgemm<2>, cudaFuncAttributeMaxDynamicSharedMemorySize, DSMEM);

    const int* src = ei;
    const int* dst = ei + E;

    const int G = (M + 127) / 128;
    const int warp_grid = (M + 7) / 8;

    // ---- prep + CSR ----
    cudaMemsetAsync(CNT, 0, (size_t)M * sizeof(int), 0);
    k_wsplit_all<<<(270336 + 255) / 256, 256>>>(emb_W, lin_l_W, lin_r_W, fus_W1, fus_W2);
    k_count<<<(E + 255) / 256, 256>>>(dst, E);
    k_xsplit<<<((M * 80) + 255) / 256, 256>>>(x, M);

    // ---- embedding: relu(x@W+b) -> REPS slice0 + RH/RL slice0 ----
    {
        SegList S;
        S.s[0] = mkseg(XH, KX, W + W_EMB_HI, KX, 5);
        S.s[1] = mkseg(XH, KX, W + W_EMB_LO, KX, 5);
        S.s[2] = mkseg(XL, KX, W + W_EMB_HI, KX, 5);
        S.n = 3; S.nk = 15;
        k_mgemm<1><<<G, 256, DSMEM>>>(S, emb_b, nullptr, nullptr, nullptr,
                                      REPS, LD, RH, RL, LD, M);
    }

    k_scan<<<1, 1024>>>(M);
    k_fill<<<(E + 255) / 256, 256>>>(src, dst, E);

    // ---- layers ----
    for (int i = 0; i < NL; i++) {
        k_agg<<<warp_grid, 256>>>(REPS + (size_t)i * HID, M);
        SegList S;
        const __nv_bfloat16* LLH = W + W_LINL(i);
        const __nv_bfloat16* LLL = LLH + 16384;
        const __nv_bfloat16* LRH = W + W_LINR(i);
        const __nv_bfloat16* LRL = LRH + 16384;
        const __nv_bfloat16* HHi = RH + (size_t)i * HID;
        const __nv_bfloat16* HLo = RL + (size_t)i * HID;
        S.s[0] = mkseg(AGGH, HID, LLH, HID, 2);
        S.s[1] = mkseg(AGGH, HID, LLL, HID, 2);
        S.s[2] = mkseg(AGGL, HID, LLH, HID, 2);
        S.s[3] = mkseg(HHi,  LD,  LRH, HID, 2);
        S.s[4] = mkseg(HHi,  LD,  LRL, HID, 2);
        S.s[5] = mkseg(HLo,  LD,  LRH, HID, 2);
        S.n = 6; S.nk = 12;
        k_mgemm<2><<<G, 256, DSMEM>>>(S, lin_l_b + (size_t)i * HID,
                                      ln_g + (size_t)i * HID, ln_b + (size_t)i * HID,
                                      (i > 0) ? (REPS + (size_t)i * HID) : nullptr,
                                      (i + 1 < NL) ? (REPS + (size_t)(i + 1) * HID) : nullptr, LD,
                                      RH + (size_t)(i + 1) * HID, RL + (size_t)(i + 1) * HID, LD, M);
    }

    // ---- fusion MLP ----
    {
        SegList S;
        S.s[0] = mkseg(RH, LD, W + W_FUS1_HI, LD, 10);
        S.s[1] = mkseg(RH, LD, W + W_FUS1_LO, LD, 10);
        S.s[2] = mkseg(RL, LD, W + W_FUS1_HI, LD, 10);
        S.n = 3; S.nk = 30;
        k_mgemm<1><<<G, 256, DSMEM>>>(S, fus_b1, nullptr, nullptr, nullptr,
                                      nullptr, 0, TMPH, TMPL, HID, M);
    }
    {
        SegList S;
        S.s[0] = mkseg(TMPH, HID, W + W_FUS2_HI, HID, 2);
        S.s[1] = mkseg(TMPH, HID, W + W_FUS2_LO, HID, 2);
        S.s[2] = mkseg(TMPL, HID, W + W_FUS2_HI, HID, 2);
        S.n = 3; S.nk = 6;
        k_mgemm<0><<<G, 256, DSMEM>>>(S, fus_b2, nullptr, nullptr, nullptr,
                                      out, HID, nullptr, nullptr, 0, M);
    }
}

// round 8
// speedup vs baseline: 1.0623x; 1.0597x over previous
#include <cuda_runtime.h>
#include <cuda_bf16.h>
#include <cstdint>
#include <math.h>

#define NN    50000
#define EE    800000
#define INDIM 300
#define HID   128
#define NL    4
#define LD    640        // (NL+1)*HID fp32 reps row
#define KX    320        // padded x width (bf16 hi/lo arrays)

// weight pack offsets (elements) — hi/lo arrays per matrix, [128][Kp] row-major
#define W_EMB_HI 0
#define W_EMB_LO 40960
#define W_LINL(i) (81920  + (i) * 32768)   // lo at +16384
#define W_LINR(i) (212992 + (i) * 32768)   // lo at +16384
#define W_FUS1_HI 344064
#define W_FUS1_LO 425984
#define W_FUS2_HI 507904
#define W_FUS2_LO 524288
#define W_TOTAL   540672

#define DSMEM (1024 + 98304)
#define MAXCH 30

// ---------------- scratch ----------------
__device__ __align__(256) float          g_REPS[(size_t)NN * LD];   // fp32 (agg gathers + skip)
__device__ __align__(256) __nv_bfloat16  g_RH  [(size_t)NN * LD];   // activation hi, ld 640
__device__ __align__(256) __nv_bfloat16  g_RL  [(size_t)NN * LD];   // activation lo, ld 640
__device__ __align__(256) __nv_bfloat16  g_XH  [(size_t)NN * KX];
__device__ __align__(256) __nv_bfloat16  g_XL  [(size_t)NN * KX];
__device__ __align__(256) __nv_bfloat16  g_AGGH[(size_t)NN * HID];
__device__ __align__(256) __nv_bfloat16  g_AGGL[(size_t)NN * HID];
__device__ __align__(256) __nv_bfloat16  g_TMPH[(size_t)NN * HID];
__device__ __align__(256) __nv_bfloat16  g_TMPL[(size_t)NN * HID];
__device__ __align__(256) __nv_bfloat16  g_W   [W_TOTAL];
__device__ float g_invdeg[NN];
__device__ int   g_cnt[NN];
__device__ int   g_cursor[NN];
__device__ int   g_rowptr[NN + 1];
__device__ int   g_col[EE];

// per-chunk pointer table, built on host, passed by value (constant bank)
struct ChunkTab {
    const __nv_bfloat16* A[MAXCH];   // pre-offset by k0
    const __nv_bfloat16* B[MAXCH];   // pre-offset by k0
    int lda[MAXCH];
    int ldb[MAXCH];
    int nk;
};

// ---------------- helpers ----------------
__device__ __forceinline__ uint32_t smem_u32(const void* p) {
    uint32_t a;
    asm("{ .reg .u64 t; cvta.to.shared.u64 t, %1; cvt.u32.u64 %0, t; }" : "=r"(a) : "l"(p));
    return a;
}
#define SW128(b) ((b) ^ (((b) >> 3) & 0x70))

__device__ __forceinline__ void cp16(uint32_t dst, const void* src, int sz) {
    asm volatile("cp.async.cg.shared.global [%0], [%1], 16, %2;"
                 :: "r"(dst), "l"(src), "r"(sz) : "memory");
}
__device__ __forceinline__ void ldm_x4(uint32_t* r, uint32_t addr) {
    asm volatile("ldmatrix.sync.aligned.m8n8.x4.shared.b16 {%0,%1,%2,%3}, [%4];"
                 : "=r"(r[0]), "=r"(r[1]), "=r"(r[2]), "=r"(r[3]) : "r"(addr));
}
__device__ __forceinline__ void ldm_x2(uint32_t* r, uint32_t addr) {
    asm volatile("ldmatrix.sync.aligned.m8n8.x2.shared.b16 {%0,%1}, [%2];"
                 : "=r"(r[0]), "=r"(r[1]) : "r"(addr));
}
__device__ __forceinline__ void mma_bf16(float* c, const uint32_t* a, const uint32_t* b) {
    asm volatile(
        "mma.sync.aligned.m16n8k16.row.col.f32.bf16.bf16.f32 "
        "{%0,%1,%2,%3}, {%4,%5,%6,%7}, {%8,%9}, {%0,%1,%2,%3};"
        : "+f"(c[0]), "+f"(c[1]), "+f"(c[2]), "+f"(c[3])
        : "r"(a[0]), "r"(a[1]), "r"(a[2]), "r"(a[3]), "r"(b[0]), "r"(b[1]));
}
__device__ __forceinline__ void split2(float v, __nv_bfloat16& hi, __nv_bfloat16& lo) {
    hi = __float2bfloat16(v);
    lo = __float2bfloat16(v - __bfloat162float(hi));
}

// ---------------- CSR build ----------------
__global__ void k_count(const int* __restrict__ dst, int E) {
    int i = blockIdx.x * blockDim.x + threadIdx.x;
    if (i < E) atomicAdd(&g_cnt[dst[i]], 1);
}

__global__ void __launch_bounds__(1024) k_scan(int M) {
    const int T = 1024;
    int t = threadIdx.x;
    int per = (M + T - 1) / T;
    int beg = t * per;
    int end = min(beg + per, M);
    int sum = 0;
    for (int i = beg; i < end; i++) sum += g_cnt[i];

    int lane = t & 31, wid = t >> 5;
    int v = sum;
    #pragma unroll
    for (int o = 1; o < 32; o <<= 1) {
        int u = __shfl_up_sync(0xffffffffu, v, o);
        if (lane >= o) v += u;
    }
    __shared__ int ws[32];
    if (lane == 31) ws[wid] = v;
    __syncthreads();
    if (wid == 0) {
        int wv = ws[lane];
        #pragma unroll
        for (int o = 1; o < 32; o <<= 1) {
            int u = __shfl_up_sync(0xffffffffu, wv, o);
            if (lane >= o) wv += u;
        }
        ws[lane] = wv;
    }
    __syncthreads();
    int run = v - sum + (wid ? ws[wid - 1] : 0);
    for (int i = beg; i < end; i++) {
        int c = g_cnt[i];
        g_rowptr[i] = run;
        g_cursor[i] = run;
        g_invdeg[i] = 1.0f / fmaxf((float)c, 1.0f);
        run += c;
    }
    if (t == T - 1) g_rowptr[M] = run;
}

__global__ void k_fill(const int* __restrict__ src, const int* __restrict__ dst, int E) {
    int i = blockIdx.x * blockDim.x + threadIdx.x;
    if (i < E) {
        int pos = atomicAdd(&g_cursor[dst[i]], 1);
        g_col[pos] = src[i];
    }
}

// ---------------- weight prep (one launch; writes hi+lo arrays) ----------------
__device__ __forceinline__ void wsplit_one(const float* W, __nv_bfloat16* ohi,
                                           __nv_bfloat16* olo, int idx, int K, int Kp) {
    int n = idx / Kp, kp = idx % Kp;
    __nv_bfloat16 hi, lo;
    if (kp < K) {
        split2(W[(size_t)kp * 128 + n], hi, lo);
    } else {
        hi = __float2bfloat16(0.f); lo = hi;
    }
    ohi[(size_t)n * Kp + kp] = hi;
    olo[(size_t)n * Kp + kp] = lo;
}

__global__ void k_wsplit_all(const float* __restrict__ emb_W,
                             const float* __restrict__ lin_l_W,
                             const float* __restrict__ lin_r_W,
                             const float* __restrict__ fus_W1,
                             const float* __restrict__ fus_W2) {
    int w = blockIdx.x * blockDim.x + threadIdx.x;
    if (w < 40960) {
        wsplit_one(emb_W, g_W + W_EMB_HI, g_W + W_EMB_LO, w, 300, 320);
    } else if (w < 106496) {
        int u = w - 40960, i = u >> 14;
        wsplit_one(lin_l_W + (size_t)i * 16384, g_W + W_LINL(i), g_W + W_LINL(i) + 16384,
                   u & 16383, 128, 128);
    } else if (w < 172032) {
        int u = w - 106496, i = u >> 14;
        wsplit_one(lin_r_W + (size_t)i * 16384, g_W + W_LINR(i), g_W + W_LINR(i) + 16384,
                   u & 16383, 128, 128);
    } else if (w < 253952) {
        wsplit_one(fus_W1, g_W + W_FUS1_HI, g_W + W_FUS1_LO, w - 172032, 640, 640);
    } else if (w < 270336) {
        wsplit_one(fus_W2, g_W + W_FUS2_HI, g_W + W_FUS2_LO, w - 253952, 128, 128);
    }
}

// x [M,300] fp32 -> XH/XL [M,320] bf16, zero pad
__global__ void k_xsplit(const float* __restrict__ x, int M) {
    int idx = blockIdx.x * blockDim.x + threadIdx.x;
    int row = idx / 80, g = idx % 80;
    if (row >= M) return;
    float vv[4] = {0.f, 0.f, 0.f, 0.f};
    if (g < 75) {
        float4 t = *reinterpret_cast<const float4*>(x + (size_t)row * INDIM + g * 4);
        vv[0] = t.x; vv[1] = t.y; vv[2] = t.z; vv[3] = t.w;
    }
    union { __nv_bfloat16 h[4]; uint2 u; } ph, pl;
    #pragma unroll
    for (int j = 0; j < 4; j++) split2(vv[j], ph.h[j], pl.h[j]);
    *reinterpret_cast<uint2*>(g_XH + (size_t)row * KX + g * 4) = ph.u;
    *reinterpret_cast<uint2*>(g_XL + (size_t)row * KX + g * 4) = pl.u;
}

// ---------------- mean aggregation (fp32 gathers) -> hi/lo bf16 ----------------
__global__ void k_agg(const float* __restrict__ H /* REPS slice, ld=LD */, int M) {
    int gw   = (blockIdx.x * blockDim.x + threadIdx.x) >> 5;
    int lane = threadIdx.x & 31;
    if (gw >= M) return;
    int beg = g_rowptr[gw], end = g_rowptr[gw + 1];
    float a0 = 0.f, a1 = 0.f, a2 = 0.f, a3 = 0.f;
    float b0 = 0.f, b1 = 0.f, b2 = 0.f, b3 = 0.f;
    for (int base = beg; base < end; base += 32) {
        int idx = (base + lane < end) ? g_col[base + lane] : 0;
        int cnt = min(32, end - base);
        int j = 0;
        for (; j + 3 < cnt; j += 4) {
            int s0 = __shfl_sync(0xffffffffu, idx, j);
            int s1 = __shfl_sync(0xffffffffu, idx, j + 1);
            int s2 = __shfl_sync(0xffffffffu, idx, j + 2);
            int s3 = __shfl_sync(0xffffffffu, idx, j + 3);
            float4 v0 = *reinterpret_cast<const float4*>(H + (size_t)s0 * LD + lane * 4);
            float4 v1 = *reinterpret_cast<const float4*>(H + (size_t)s1 * LD + lane * 4);
            float4 v2 = *reinterpret_cast<const float4*>(H + (size_t)s2 * LD + lane * 4);
            float4 v3 = *reinterpret_cast<const float4*>(H + (size_t)s3 * LD + lane * 4);
            a0 += v0.x; a1 += v0.y; a2 += v0.z; a3 += v0.w;
            b0 += v1.x; b1 += v1.y; b2 += v1.z; b3 += v1.w;
            a0 += v2.x; a1 += v2.y; a2 += v2.z; a3 += v2.w;
            b0 += v3.x; b1 += v3.y; b2 += v3.z; b3 += v3.w;
        }
        for (; j < cnt; j++) {
            int s = __shfl_sync(0xffffffffu, idx, j);
            float4 v = *reinterpret_cast<const float4*>(H + (size_t)s * LD + lane * 4);
            a0 += v.x; a1 += v.y; a2 += v.z; a3 += v.w;
        }
    }
    a0 += b0; a1 += b1; a2 += b2; a3 += b3;
    float w = g_invdeg[gw];
    float m[4] = {a0 * w, a1 * w, a2 * w, a3 * w};
    union { __nv_bfloat16 h[4]; uint2 u; } ph, pl;
    #pragma unroll
    for (int j = 0; j < 4; j++) split2(m[j], ph.h[j], pl.h[j]);
    *reinterpret_cast<uint2*>(g_AGGH + (size_t)gw * HID + lane * 4) = ph.u;
    *reinterpret_cast<uint2*>(g_AGGL + (size_t)gw * HID + lane * 4) = pl.u;
}

// ---------------- tile loader ----------------
__device__ __forceinline__ void load_tiles(uint32_t tiles, int s, int tid, int m0, int M,
                                           const __nv_bfloat16* A, int lda,
                                           const __nv_bfloat16* B, int ldb) {
    uint32_t abase = tiles + (uint32_t)s * 32768u;
    uint32_t bbase = abase + 16384u;
    #pragma unroll
    for (int i = 0; i < 4; i++) {
        int v = tid + i * 256;
        int r = v >> 3, ch = v & 7;
        uint32_t bo = (uint32_t)(r * 128 + ch * 16);
        int row = m0 + r;
        int rc = row < M ? row : 0;
        const __nv_bfloat16* src = A + (size_t)rc * lda + ch * 8;
        cp16(abase + SW128(bo), src, row < M ? 16 : 0);
    }
    #pragma unroll
    for (int i = 0; i < 4; i++) {
        int v = tid + i * 256;
        int r = v >> 3, ch = v & 7;
        uint32_t bo = (uint32_t)(r * 128 + ch * 16);
        cp16(bbase + SW128(bo), B + (size_t)r * ldb + ch * 8, 16);
    }
    asm volatile("cp.async.commit_group;" ::: "memory");
}

// ---------------- mma.sync GEMM, 128x128 tile, BK=64, 3-stage, chunk table ----------------
// MODE 0: C + bias                              -> outF
// MODE 1: relu(C + bias)                        -> [outF] + (outH,outL)
// MODE 2: LN(C + bias)*g+b (+skip), relu        -> [outF] + (outH,outL)
template <int MODE>
__global__ void __launch_bounds__(256)
k_mgemm(ChunkTab ct,
        const float* __restrict__ bias, const float* __restrict__ lng, const float* __restrict__ lnb,
        const float* __restrict__ skip, float* __restrict__ outF, int ldF,
        __nv_bfloat16* __restrict__ outH, __nv_bfloat16* __restrict__ outL, int ldo, int M) {
    extern __shared__ char smem_raw[];
    char* smem = (char*)(((uintptr_t)smem_raw + 1023) & ~(uintptr_t)1023);
    const uint32_t tiles = smem_u32(smem);

    const int tid  = threadIdx.x;
    const int lane = tid & 31, wid = tid >> 5;
    const int m0   = blockIdx.x * 128;

    const int wm = (wid & 1) * 64;
    const int wn = (wid >> 1) * 32;

    float acc[4][4][4];
    #pragma unroll
    for (int i = 0; i < 4; i++)
        #pragma unroll
        for (int j = 0; j < 4; j++)
            #pragma unroll
            for (int q = 0; q < 4; q++) acc[i][j][q] = 0.f;

    const int nk = ct.nk;

    const int r_in = ((lane >> 3) & 1) * 8 + (lane & 7);
    const int ca8  = (lane >> 4) * 8;
    const int rb   = lane & 7;
    const int cb8  = ((lane >> 3) & 1) * 8;

    load_tiles(tiles, 0, tid, m0, M, ct.A[0], ct.lda[0], ct.B[0], ct.ldb[0]);
    if (nk > 1) load_tiles(tiles, 1, tid, m0, M, ct.A[1], ct.lda[1], ct.B[1], ct.ldb[1]);

    #pragma unroll 1
    for (int c = 0; c < nk; c++) {
        if (c + 1 < nk) asm volatile("cp.async.wait_group 1;" ::: "memory");
        else            asm volatile("cp.async.wait_group 0;" ::: "memory");
        __syncthreads();
        if (c + 2 < nk) {
            int cn = c + 2;
            load_tiles(tiles, cn % 3, tid, m0, M, ct.A[cn], ct.lda[cn], ct.B[cn], ct.ldb[cn]);
        }

        uint32_t abase = tiles + (uint32_t)(c % 3) * 32768u;
        uint32_t bbase = abase + 16384u;
        #pragma unroll
        for (int ka = 0; ka < 4; ka++) {
            uint32_t a[4][4];
            #pragma unroll
            for (int ma = 0; ma < 4; ma++) {
                int r = wm + ma * 16 + r_in, cc = ka * 16 + ca8;
                ldm_x4(a[ma], abase + SW128((uint32_t)(r * 128 + cc * 2)));
            }
            uint32_t b[4][2];
            #pragma unroll
            for (int na = 0; na < 4; na++) {
                int r = wn + na * 8 + rb, cc = ka * 16 + cb8;
                ldm_x2(b[na], bbase + SW128((uint32_t)(r * 128 + cc * 2)));
            }
            #pragma unroll
            for (int ma = 0; ma < 4; ma++)
                #pragma unroll
                for (int na = 0; na < 4; na++)
                    mma_bf16(acc[ma][na], a[ma], b[na]);
        }
    }
    __syncthreads();

    // park accumulators in smem C [128][132] fp32
    float* C = (float*)smem;
    #pragma unroll
    for (int ma = 0; ma < 4; ma++)
        #pragma unroll
        for (int na = 0; na < 4; na++) {
            int r0 = wm + ma * 16 + (lane >> 2);
            int cc = wn + na * 8 + 2 * (lane & 3);
            C[r0 * 132 + cc]           = acc[ma][na][0];
            C[r0 * 132 + cc + 1]       = acc[ma][na][1];
            C[(r0 + 8) * 132 + cc]     = acc[ma][na][2];
            C[(r0 + 8) * 132 + cc + 1] = acc[ma][na][3];
        }
    __syncthreads();

    // epilogue: warp per row
    #pragma unroll 1
    for (int t = 0; t < 16; t++) {
        int rr  = wid + t * 8;
        int row = m0 + rr;
        if (row >= M) continue;
        float4 v = *reinterpret_cast<float4*>(C + rr * 132 + lane * 4);
        float4 bb = *reinterpret_cast<const float4*>(bias + lane * 4);
        v.x += bb.x; v.y += bb.y; v.z += bb.z; v.w += bb.w;
        if (MODE == 2) {
            float s  = v.x + v.y + v.z + v.w;
            float ss = v.x * v.x + v.y * v.y + v.z * v.z + v.w * v.w;
            #pragma unroll
            for (int off = 16; off; off >>= 1) {
                s  += __shfl_xor_sync(0xffffffffu, s,  off);
                ss += __shfl_xor_sync(0xffffffffu, ss, off);
            }
            float mu  = s * (1.0f / 128.0f);
            float var = ss * (1.0f / 128.0f) - mu * mu;
            float inv = rsqrtf(var + 1e-5f);
            float4 gg = *reinterpret_cast<const float4*>(lng + lane * 4);
            float4 ob = *reinterpret_cast<const float4*>(lnb + lane * 4);
            v.x = (v.x - mu) * inv * gg.x + ob.x;
            v.y = (v.y - mu) * inv * gg.y + ob.y;
            v.z = (v.z - mu) * inv * gg.z + ob.z;
            v.w = (v.w - mu) * inv * gg.w + ob.w;
            if (skip) {
                float4 sk = *reinterpret_cast<const float4*>(skip + (size_t)row * LD + lane * 4);
                v.x += sk.x; v.y += sk.y; v.z += sk.z; v.w += sk.w;
            }
        }
        if (MODE != 0) {
            v.x = fmaxf(v.x, 0.f); v.y = fmaxf(v.y, 0.f);
            v.z = fmaxf(v.z, 0.f); v.w = fmaxf(v.w, 0.f);
        }
        if (outF) {
            *reinterpret_cast<float4*>(outF + (size_t)row * ldF + lane * 4) = v;
        }
        if (MODE != 0) {
            union { __nv_bfloat16 h[4]; uint2 u; } ph, pl;
            float vv[4] = {v.x, v.y, v.z, v.w};
            #pragma unroll
            for (int jj = 0; jj < 4; jj++) split2(vv[jj], ph.h[jj], pl.h[jj]);
            *reinterpret_cast<uint2*>(outH + (size_t)row * ldo + lane * 4) = ph.u;
            *reinterpret_cast<uint2*>(outL + (size_t)row * ldo + lane * 4) = pl.u;
        }
    }
}

// host-side chunk table builder: append one segment (nch chunks of K=64)
static inline void add_seg(ChunkTab& ct, const __nv_bfloat16* A, int lda,
                           const __nv_bfloat16* B, int ldb, int nch) {
    for (int c = 0; c < nch; c++) {
        ct.A[ct.nk]   = A + c * 64;
        ct.B[ct.nk]   = B + c * 64;
        ct.lda[ct.nk] = lda;
        ct.ldb[ct.nk] = ldb;
        ct.nk++;
    }
}

// ---------------- launch ----------------
extern "C" void kernel_launch(void* const* d_in, const int* in_sizes, int n_in,
                              void* d_out, int out_size) {
    const float* x       = (const float*)d_in[0];
    const int*   ei      = (const int*)  d_in[1];
    const float* emb_W   = (const float*)d_in[2];
    const float* emb_b   = (const float*)d_in[3];
    const float* lin_l_W = (const float*)d_in[4];
    const float* lin_l_b = (const float*)d_in[5];
    const float* lin_r_W = (const float*)d_in[6];
    const float* ln_g    = (const float*)d_in[7];
    const float* ln_b    = (const float*)d_in[8];
    const float* fus_W1  = (const float*)d_in[9];
    const float* fus_b1  = (const float*)d_in[10];
    const float* fus_W2  = (const float*)d_in[11];
    const float* fus_b2  = (const float*)d_in[12];
    float* out = (float*)d_out;

    const int M = in_sizes[0] / INDIM;
    const int E = in_sizes[1] / 2;

    float *REPS; __nv_bfloat16 *RH, *RL, *XH, *XL, *AGGH, *AGGL, *TMPH, *TMPL, *W;
    int *CNT;
    cudaGetSymbolAddress((void**)&REPS, g_REPS);
    cudaGetSymbolAddress((void**)&RH,   g_RH);
    cudaGetSymbolAddress((void**)&RL,   g_RL);
    cudaGetSymbolAddress((void**)&XH,   g_XH);
    cudaGetSymbolAddress((void**)&XL,   g_XL);
    cudaGetSymbolAddress((void**)&AGGH, g_AGGH);
    cudaGetSymbolAddress((void**)&AGGL, g_AGGL);
    cudaGetSymbolAddress((void**)&TMPH, g_TMPH);
    cudaGetSymbolAddress((void**)&TMPL, g_TMPL);
    cudaGetSymbolAddress((void**)&W,    g_W);
    cudaGetSymbolAddress((void**)&CNT,  g_cnt);

    cudaFuncSetAttribute(k_mgemm<0>, cudaFuncAttributeMaxDynamicSharedMemorySize, DSMEM);
    cudaFuncSetAttribute(k_mgemm<1>, cudaFuncAttributeMaxDynamicSharedMemorySize, DSMEM);
    cudaFuncSetAttribute(k_mgemm<2>, cudaFuncAttributeMaxDynamicSharedMemorySize, DSMEM);

    const int* src = ei;
    const int* dst = ei + E;

    const int G = (M + 127) / 128;
    const int warp_grid = (M + 7) / 8;

    // ---- prep + CSR ----
    cudaMemsetAsync(CNT, 0, (size_t)M * sizeof(int), 0);
    k_wsplit_all<<<(270336 + 255) / 256, 256>>>(emb_W, lin_l_W, lin_r_W, fus_W1, fus_W2);
    k_count<<<(E + 255) / 256, 256>>>(dst, E);
    k_xsplit<<<((M * 80) + 255) / 256, 256>>>(x, M);

    // ---- embedding: relu(x@W+b) -> REPS slice0 + RH/RL slice0 ----
    {
        ChunkTab ct; ct.nk = 0;
        add_seg(ct, XH, KX, W + W_EMB_HI, KX, 5);
        add_seg(ct, XH, KX, W + W_EMB_LO, KX, 5);
        add_seg(ct, XL, KX, W + W_EMB_HI, KX, 5);
        k_mgemm<1><<<G, 256, DSMEM>>>(ct, emb_b, nullptr, nullptr, nullptr,
                                      REPS, LD, RH, RL, LD, M);
    }

    k_scan<<<1, 1024>>>(M);
    k_fill<<<(E + 255) / 256, 256>>>(src, dst, E);

    // ---- layers ----
    for (int i = 0; i < NL; i++) {
        k_agg<<<warp_grid, 256>>>(REPS + (size_t)i * HID, M);
        ChunkTab ct; ct.nk = 0;
        const __nv_bfloat16* LLH = W + W_LINL(i);
        const __nv_bfloat16* LLL = LLH + 16384;
        const __nv_bfloat16* LRH = W + W_LINR(i);
        const __nv_bfloat16* LRL = LRH + 16384;
        const __nv_bfloat16* HHi = RH + (size_t)i * HID;
        const __nv_bfloat16* HLo = RL + (size_t)i * HID;
        add_seg(ct, AGGH, HID, LLH, HID, 2);
        add_seg(ct, AGGH, HID, LLL, HID, 2);
        add_seg(ct, AGGL, HID, LLH, HID, 2);
        add_seg(ct, HHi,  LD,  LRH, HID, 2);
        add_seg(ct, HHi,  LD,  LRL, HID, 2);
        add_seg(ct, HLo,  LD,  LRH, HID, 2);
        k_mgemm<2><<<G, 256, DSMEM>>>(ct, lin_l_b + (size_t)i * HID,
                                      ln_g + (size_t)i * HID, ln_b + (size_t)i * HID,
                                      (i > 0) ? (REPS + (size_t)i * HID) : nullptr,
                                      (i + 1 < NL) ? (REPS + (size_t)(i + 1) * HID) : nullptr, LD,
                                      RH + (size_t)(i + 1) * HID, RL + (size_t)(i + 1) * HID, LD, M);
    }

    // ---- fusion MLP ----
    {
        ChunkTab ct; ct.nk = 0;
        add_seg(ct, RH, LD, W + W_FUS1_HI, LD, 10);
        add_seg(ct, RH, LD, W + W_FUS1_LO, LD, 10);
        add_seg(ct, RL, LD, W + W_FUS1_HI, LD, 10);
        k_mgemm<1><<<G, 256, DSMEM>>>(ct, fus_b1, nullptr, nullptr, nullptr,
                                      nullptr, 0, TMPH, TMPL, HID, M);
    }
    {
        ChunkTab ct; ct.nk = 0;
        add_seg(ct, TMPH, HID, W + W_FUS2_HI, HID, 2);
        add_seg(ct, TMPH, HID, W + W_FUS2_LO, HID, 2);
        add_seg(ct, TMPL, HID, W + W_FUS2_HI, HID, 2);
        k_mgemm<0><<<G, 256, DSMEM>>>(ct, fus_b2, nullptr, nullptr, nullptr,
                                      out, HID, nullptr, nullptr, 0, M);
    }
}

// round 9
// speedup vs baseline: 1.1771x; 1.1081x over previous
#include <cuda_runtime.h>
#include <cuda_bf16.h>
#include <cstdint>
#include <math.h>

#define NN    50000
#define EE    800000
#define INDIM 300
#define HID   128
#define NL    4
#define LD    640        // (NL+1)*HID fp32 reps row
#define KX    320        // padded x width (bf16 hi/lo arrays)

// weight pack offsets (elements) — hi/lo arrays per matrix, [128][Kp] row-major
#define W_EMB_HI 0
#define W_EMB_LO 40960
#define W_LINL(i) (81920  + (i) * 32768)   // lo at +16384
#define W_LINR(i) (212992 + (i) * 32768)   // lo at +16384
#define W_FUS1_HI 344064
#define W_FUS1_LO 425984
#define W_FUS2_HI 507904
#define W_FUS2_LO 524288
#define W_TOTAL   540672

#define DSMEM (1024 + 98304)
#define MAXCH 30

// ---------------- scratch ----------------
__device__ __align__(256) float          g_REPS[(size_t)NN * LD];   // fp32 (agg gathers + skip)
__device__ __align__(256) __nv_bfloat16  g_RH  [(size_t)NN * LD];   // activation hi, ld 640
__device__ __align__(256) __nv_bfloat16  g_RL  [(size_t)NN * LD];   // activation lo, ld 640
__device__ __align__(256) __nv_bfloat16  g_XH  [(size_t)NN * KX];
__device__ __align__(256) __nv_bfloat16  g_XL  [(size_t)NN * KX];
__device__ __align__(256) __nv_bfloat16  g_AGGH[(size_t)NN * HID];
__device__ __align__(256) __nv_bfloat16  g_AGGL[(size_t)NN * HID];
__device__ __align__(256) __nv_bfloat16  g_TMPH[(size_t)NN * HID];
__device__ __align__(256) __nv_bfloat16  g_TMPL[(size_t)NN * HID];
__device__ __align__(256) __nv_bfloat16  g_W   [W_TOTAL];
__device__ float g_invdeg[NN];
__device__ int   g_cnt[NN];
__device__ int   g_cursor[NN];
__device__ int   g_rowptr[NN + 1];
__device__ int   g_col[EE];

// per-chunk pointer table, built on host, passed by value (constant bank)
struct ChunkTab {
    const __nv_bfloat16* A[MAXCH];   // pre-offset by k0
    const __nv_bfloat16* B[MAXCH];   // pre-offset by k0
    int lda[MAXCH];
    int ldb[MAXCH];
    int nk;
};

// ---------------- helpers ----------------
__device__ __forceinline__ uint32_t smem_u32(const void* p) {
    uint32_t a;
    asm("{ .reg .u64 t; cvta.to.shared.u64 t, %1; cvt.u32.u64 %0, t; }" : "=r"(a) : "l"(p));
    return a;
}
#define SW128(b) ((b) ^ (((b) >> 3) & 0x70))

__device__ __forceinline__ void cp16(uint32_t dst, const void* src, int sz) {
    asm volatile("cp.async.cg.shared.global [%0], [%1], 16, %2;"
                 :: "r"(dst), "l"(src), "r"(sz) : "memory");
}
__device__ __forceinline__ void ldm_x4(uint32_t* r, uint32_t addr) {
    asm volatile("ldmatrix.sync.aligned.m8n8.x4.shared.b16 {%0,%1,%2,%3}, [%4];"
                 : "=r"(r[0]), "=r"(r[1]), "=r"(r[2]), "=r"(r[3]) : "r"(addr));
}
__device__ __forceinline__ void ldm_x2(uint32_t* r, uint32_t addr) {
    asm volatile("ldmatrix.sync.aligned.m8n8.x2.shared.b16 {%0,%1}, [%2];"
                 : "=r"(r[0]), "=r"(r[1]) : "r"(addr));
}
__device__ __forceinline__ void mma_bf16(float* c, const uint32_t* a, const uint32_t* b) {
    asm volatile(
        "mma.sync.aligned.m16n8k16.row.col.f32.bf16.bf16.f32 "
        "{%0,%1,%2,%3}, {%4,%5,%6,%7}, {%8,%9}, {%0,%1,%2,%3};"
        : "+f"(c[0]), "+f"(c[1]), "+f"(c[2]), "+f"(c[3])
        : "r"(a[0]), "r"(a[1]), "r"(a[2]), "r"(a[3]), "r"(b[0]), "r"(b[1]));
}
__device__ __forceinline__ void split2(float v, __nv_bfloat16& hi, __nv_bfloat16& lo) {
    hi = __float2bfloat16(v);
    lo = __float2bfloat16(v - __bfloat162float(hi));
}

// ---------------- CSR build ----------------
__global__ void k_count(const int* __restrict__ dst, int E) {
    int i = blockIdx.x * blockDim.x + threadIdx.x;
    if (i < E) atomicAdd(&g_cnt[dst[i]], 1);
}

__global__ void __launch_bounds__(1024) k_scan(int M) {
    const int T = 1024;
    int t = threadIdx.x;
    int per = (M + T - 1) / T;
    int beg = t * per;
    int end = min(beg + per, M);
    int sum = 0;
    for (int i = beg; i < end; i++) sum += g_cnt[i];

    int lane = t & 31, wid = t >> 5;
    int v = sum;
    #pragma unroll
    for (int o = 1; o < 32; o <<= 1) {
        int u = __shfl_up_sync(0xffffffffu, v, o);
        if (lane >= o) v += u;
    }
    __shared__ int ws[32];
    if (lane == 31) ws[wid] = v;
    __syncthreads();
    if (wid == 0) {
        int wv = ws[lane];
        #pragma unroll
        for (int o = 1; o < 32; o <<= 1) {
            int u = __shfl_up_sync(0xffffffffu, wv, o);
            if (lane >= o) wv += u;
        }
        ws[lane] = wv;
    }
    __syncthreads();
    int run = v - sum + (wid ? ws[wid - 1] : 0);
    for (int i = beg; i < end; i++) {
        int c = g_cnt[i];
        g_rowptr[i] = run;
        g_cursor[i] = run;
        g_invdeg[i] = 1.0f / fmaxf((float)c, 1.0f);
        run += c;
    }
    if (t == T - 1) g_rowptr[M] = run;
}

__global__ void k_fill(const int* __restrict__ src, const int* __restrict__ dst, int E) {
    int i = blockIdx.x * blockDim.x + threadIdx.x;
    if (i < E) {
        int pos = atomicAdd(&g_cursor[dst[i]], 1);
        g_col[pos] = src[i];
    }
}

// ---------------- weight prep (one launch; writes hi+lo arrays) ----------------
__device__ __forceinline__ void wsplit_one(const float* W, __nv_bfloat16* ohi,
                                           __nv_bfloat16* olo, int idx, int K, int Kp) {
    int n = idx / Kp, kp = idx % Kp;
    __nv_bfloat16 hi, lo;
    if (kp < K) {
        split2(W[(size_t)kp * 128 + n], hi, lo);
    } else {
        hi = __float2bfloat16(0.f); lo = hi;
    }
    ohi[(size_t)n * Kp + kp] = hi;
    olo[(size_t)n * Kp + kp] = lo;
}

__global__ void k_wsplit_all(const float* __restrict__ emb_W,
                             const float* __restrict__ lin_l_W,
                             const float* __restrict__ lin_r_W,
                             const float* __restrict__ fus_W1,
                             const float* __restrict__ fus_W2) {
    int w = blockIdx.x * blockDim.x + threadIdx.x;
    if (w < 40960) {
        wsplit_one(emb_W, g_W + W_EMB_HI, g_W + W_EMB_LO, w, 300, 320);
    } else if (w < 106496) {
        int u = w - 40960, i = u >> 14;
        wsplit_one(lin_l_W + (size_t)i * 16384, g_W + W_LINL(i), g_W + W_LINL(i) + 16384,
                   u & 16383, 128, 128);
    } else if (w < 172032) {
        int u = w - 106496, i = u >> 14;
        wsplit_one(lin_r_W + (size_t)i * 16384, g_W + W_LINR(i), g_W + W_LINR(i) + 16384,
                   u & 16383, 128, 128);
    } else if (w < 253952) {
        wsplit_one(fus_W1, g_W + W_FUS1_HI, g_W + W_FUS1_LO, w - 172032, 640, 640);
    } else if (w < 270336) {
        wsplit_one(fus_W2, g_W + W_FUS2_HI, g_W + W_FUS2_LO, w - 253952, 128, 128);
    }
}

// x [M,300] fp32 -> XH/XL [M,320] bf16, zero pad
__global__ void k_xsplit(const float* __restrict__ x, int M) {
    int idx = blockIdx.x * blockDim.x + threadIdx.x;
    int row = idx / 80, g = idx % 80;
    if (row >= M) return;
    float vv[4] = {0.f, 0.f, 0.f, 0.f};
    if (g < 75) {
        float4 t = *reinterpret_cast<const float4*>(x + (size_t)row * INDIM + g * 4);
        vv[0] = t.x; vv[1] = t.y; vv[2] = t.z; vv[3] = t.w;
    }
    union { __nv_bfloat16 h[4]; uint2 u; } ph, pl;
    #pragma unroll
    for (int j = 0; j < 4; j++) split2(vv[j], ph.h[j], pl.h[j]);
    *reinterpret_cast<uint2*>(g_XH + (size_t)row * KX + g * 4) = ph.u;
    *reinterpret_cast<uint2*>(g_XL + (size_t)row * KX + g * 4) = pl.u;
}

// ---------------- mean aggregation (fp32 gathers) -> hi/lo bf16 ----------------
__global__ void k_agg(const float* __restrict__ H /* REPS slice, ld=LD */, int M) {
    int gw   = (blockIdx.x * blockDim.x + threadIdx.x) >> 5;
    int lane = threadIdx.x & 31;
    if (gw >= M) return;
    int beg = g_rowptr[gw], end = g_rowptr[gw + 1];
    float a0 = 0.f, a1 = 0.f, a2 = 0.f, a3 = 0.f;
    float b0 = 0.f, b1 = 0.f, b2 = 0.f, b3 = 0.f;
    for (int base = beg; base < end; base += 32) {
        int idx = (base + lane < end) ? g_col[base + lane] : 0;
        int cnt = min(32, end - base);
        int j = 0;
        for (; j + 3 < cnt; j += 4) {
            int s0 = __shfl_sync(0xffffffffu, idx, j);
            int s1 = __shfl_sync(0xffffffffu, idx, j + 1);
            int s2 = __shfl_sync(0xffffffffu, idx, j + 2);
            int s3 = __shfl_sync(0xffffffffu, idx, j + 3);
            float4 v0 = *reinterpret_cast<const float4*>(H + (size_t)s0 * LD + lane * 4);
            float4 v1 = *reinterpret_cast<const float4*>(H + (size_t)s1 * LD + lane * 4);
            float4 v2 = *reinterpret_cast<const float4*>(H + (size_t)s2 * LD + lane * 4);
            float4 v3 = *reinterpret_cast<const float4*>(H + (size_t)s3 * LD + lane * 4);
            a0 += v0.x; a1 += v0.y; a2 += v0.z; a3 += v0.w;
            b0 += v1.x; b1 += v1.y; b2 += v1.z; b3 += v1.w;
            a0 += v2.x; a1 += v2.y; a2 += v2.z; a3 += v2.w;
            b0 += v3.x; b1 += v3.y; b2 += v3.z; b3 += v3.w;
        }
        for (; j < cnt; j++) {
            int s = __shfl_sync(0xffffffffu, idx, j);
            float4 v = *reinterpret_cast<const float4*>(H + (size_t)s * LD + lane * 4);
            a0 += v.x; a1 += v.y; a2 += v.z; a3 += v.w;
        }
    }
    a0 += b0; a1 += b1; a2 += b2; a3 += b3;
    float w = g_invdeg[gw];
    float m[4] = {a0 * w, a1 * w, a2 * w, a3 * w};
    union { __nv_bfloat16 h[4]; uint2 u; } ph, pl;
    #pragma unroll
    for (int j = 0; j < 4; j++) split2(m[j], ph.h[j], pl.h[j]);
    *reinterpret_cast<uint2*>(g_AGGH + (size_t)gw * HID + lane * 4) = ph.u;
    *reinterpret_cast<uint2*>(g_AGGL + (size_t)gw * HID + lane * 4) = pl.u;
}

// ---------------- tile loader (32-bit address math) ----------------
__device__ __forceinline__ void load_tiles(uint32_t tiles, int s, int tid, int m0, int M,
                                           const __nv_bfloat16* A, int lda,
                                           const __nv_bfloat16* B, int ldb) {
    uint32_t abase = tiles + (uint32_t)s * 32768u;
    uint32_t bbase = abase + 16384u;
    #pragma unroll
    for (int i = 0; i < 4; i++) {
        int v = tid + i * 256;
        int r = v >> 3, ch = v & 7;
        uint32_t bo = (uint32_t)(r * 128 + ch * 16);
        int row = m0 + r;
        int rc = row < M ? row : 0;
        cp16(abase + SW128(bo), A + (rc * lda + ch * 8), row < M ? 16 : 0);
    }
    #pragma unroll
    for (int i = 0; i < 4; i++) {
        int v = tid + i * 256;
        int r = v >> 3, ch = v & 7;
        uint32_t bo = (uint32_t)(r * 128 + ch * 16);
        cp16(bbase + SW128(bo), B + (r * ldb + ch * 8), 16);
    }
    asm volatile("cp.async.commit_group;" ::: "memory");
}

// ---------------- mma.sync GEMM, 128x128 tile, BK=64, 3-stage, chunk table ----------------
// MODE 0: C + bias                              -> outF
// MODE 1: relu(C + bias)                        -> [outF] + (outH,outL)
// MODE 2: LN(C + bias)*g+b (+skip), relu        -> [outF] + (outH,outL)
template <int MODE>
__global__ void __launch_bounds__(256, 2)
k_mgemm(ChunkTab ct,
        const float* __restrict__ bias, const float* __restrict__ lng, const float* __restrict__ lnb,
        const float* __restrict__ skip, float* __restrict__ outF, int ldF,
        __nv_bfloat16* __restrict__ outH, __nv_bfloat16* __restrict__ outL, int ldo, int M) {
    extern __shared__ char smem_raw[];
    char* smem = (char*)(((uintptr_t)smem_raw + 1023) & ~(uintptr_t)1023);
    const uint32_t tiles = smem_u32(smem);

    const int tid  = threadIdx.x;
    const int lane = tid & 31, wid = tid >> 5;
    const int m0   = blockIdx.x * 128;

    const int wm = (wid & 1) * 64;
    const int wn = (wid >> 1) * 32;

    float acc[4][4][4];
    #pragma unroll
    for (int i = 0; i < 4; i++)
        #pragma unroll
        for (int j = 0; j < 4; j++)
            #pragma unroll
            for (int q = 0; q < 4; q++) acc[i][j][q] = 0.f;

    const int nk = ct.nk;

    const int r_in = ((lane >> 3) & 1) * 8 + (lane & 7);
    const int ca8  = (lane >> 4) * 8;
    const int rb   = lane & 7;
    const int cb8  = ((lane >> 3) & 1) * 8;

    load_tiles(tiles, 0, tid, m0, M, ct.A[0], ct.lda[0], ct.B[0], ct.ldb[0]);
    if (nk > 1) load_tiles(tiles, 1, tid, m0, M, ct.A[1], ct.lda[1], ct.B[1], ct.ldb[1]);

    #pragma unroll 1
    for (int c = 0; c < nk; c++) {
        if (c + 1 < nk) asm volatile("cp.async.wait_group 1;" ::: "memory");
        else            asm volatile("cp.async.wait_group 0;" ::: "memory");
        __syncthreads();
        if (c + 2 < nk) {
            int cn = c + 2;
            load_tiles(tiles, cn % 3, tid, m0, M, ct.A[cn], ct.lda[cn], ct.B[cn], ct.ldb[cn]);
        }

        uint32_t abase = tiles + (uint32_t)(c % 3) * 32768u;
        uint32_t bbase = abase + 16384u;
        #pragma unroll
        for (int ka = 0; ka < 4; ka++) {
            uint32_t a[4][4];
            #pragma unroll
            for (int ma = 0; ma < 4; ma++) {
                int r = wm + ma * 16 + r_in, cc = ka * 16 + ca8;
                ldm_x4(a[ma], abase + SW128((uint32_t)(r * 128 + cc * 2)));
            }
            uint32_t b[4][2];
            #pragma unroll
            for (int na = 0; na < 4; na++) {
                int r = wn + na * 8 + rb, cc = ka * 16 + cb8;
                ldm_x2(b[na], bbase + SW128((uint32_t)(r * 128 + cc * 2)));
            }
            #pragma unroll
            for (int ma = 0; ma < 4; ma++)
                #pragma unroll
                for (int na = 0; na < 4; na++)
                    mma_bf16(acc[ma][na], a[ma], b[na]);
        }
    }
    __syncthreads();

    // park accumulators in smem C [128][132] fp32
    float* C = (float*)smem;
    #pragma unroll
    for (int ma = 0; ma < 4; ma++)
        #pragma unroll
        for (int na = 0; na < 4; na++) {
            int r0 = wm + ma * 16 + (lane >> 2);
            int cc = wn + na * 8 + 2 * (lane & 3);
            C[r0 * 132 + cc]           = acc[ma][na][0];
            C[r0 * 132 + cc + 1]       = acc[ma][na][1];
            C[(r0 + 8) * 132 + cc]     = acc[ma][na][2];
            C[(r0 + 8) * 132 + cc + 1] = acc[ma][na][3];
        }
    __syncthreads();

    // epilogue: warp per row
    #pragma unroll 1
    for (int t = 0; t < 16; t++) {
        int rr  = wid + t * 8;
        int row = m0 + rr;
        if (row >= M) continue;
        float4 v = *reinterpret_cast<float4*>(C + rr * 132 + lane * 4);
        float4 bb = *reinterpret_cast<const float4*>(bias + lane * 4);
        v.x += bb.x; v.y += bb.y; v.z += bb.z; v.w += bb.w;
        if (MODE == 2) {
            float s  = v.x + v.y + v.z + v.w;
            float ss = v.x * v.x + v.y * v.y + v.z * v.z + v.w * v.w;
            #pragma unroll
            for (int off = 16; off; off >>= 1) {
                s  += __shfl_xor_sync(0xffffffffu, s,  off);
                ss += __shfl_xor_sync(0xffffffffu, ss, off);
            }
            float mu  = s * (1.0f / 128.0f);
            float var = ss * (1.0f / 128.0f) - mu * mu;
            float inv = rsqrtf(var + 1e-5f);
            float4 gg = *reinterpret_cast<const float4*>(lng + lane * 4);
            float4 ob = *reinterpret_cast<const float4*>(lnb + lane * 4);
            v.x = (v.x - mu) * inv * gg.x + ob.x;
            v.y = (v.y - mu) * inv * gg.y + ob.y;
            v.z = (v.z - mu) * inv * gg.z + ob.z;
            v.w = (v.w - mu) * inv * gg.w + ob.w;
            if (skip) {
                float4 sk = *reinterpret_cast<const float4*>(skip + (size_t)row * LD + lane * 4);
                v.x += sk.x; v.y += sk.y; v.z += sk.z; v.w += sk.w;
            }
        }
        if (MODE != 0) {
            v.x = fmaxf(v.x, 0.f); v.y = fmaxf(v.y, 0.f);
            v.z = fmaxf(v.z, 0.f); v.w = fmaxf(v.w, 0.f);
        }
        if (outF) {
            *reinterpret_cast<float4*>(outF + (size_t)row * ldF + lane * 4) = v;
        }
        if (MODE != 0) {
            union { __nv_bfloat16 h[4]; uint2 u; } ph, pl;
            float vv[4] = {v.x, v.y, v.z, v.w};
            #pragma unroll
            for (int jj = 0; jj < 4; jj++) split2(vv[jj], ph.h[jj], pl.h[jj]);
            *reinterpret_cast<uint2*>(outH + (size_t)row * ldo + lane * 4) = ph.u;
            *reinterpret_cast<uint2*>(outL + (size_t)row * ldo + lane * 4) = pl.u;
        }
    }
}

// host-side chunk table builder: append one segment (nch chunks of K=64)
static inline void add_seg(ChunkTab& ct, const __nv_bfloat16* A, int lda,
                           const __nv_bfloat16* B, int ldb, int nch) {
    for (int c = 0; c < nch; c++) {
        ct.A[ct.nk]   = A + c * 64;
        ct.B[ct.nk]   = B + c * 64;
        ct.lda[ct.nk] = lda;
        ct.ldb[ct.nk] = ldb;
        ct.nk++;
    }
}

// ---------------- launch ----------------
extern "C" void kernel_launch(void* const* d_in, const int* in_sizes, int n_in,
                              void* d_out, int out_size) {
    const float* x       = (const float*)d_in[0];
    const int*   ei      = (const int*)  d_in[1];
    const float* emb_W   = (const float*)d_in[2];
    const float* emb_b   = (const float*)d_in[3];
    const float* lin_l_W = (const float*)d_in[4];
    const float* lin_l_b = (const float*)d_in[5];
    const float* lin_r_W = (const float*)d_in[6];
    const float* ln_g    = (const float*)d_in[7];
    const float* ln_b    = (const float*)d_in[8];
    const float* fus_W1  = (const float*)d_in[9];
    const float* fus_b1  = (const float*)d_in[10];
    const float* fus_W2  = (const float*)d_in[11];
    const float* fus_b2  = (const float*)d_in[12];
    float* out = (float*)d_out;

    const int M = in_sizes[0] / INDIM;
    const int E = in_sizes[1] / 2;

    float *REPS; __nv_bfloat16 *RH, *RL, *XH, *XL, *AGGH, *AGGL, *TMPH, *TMPL, *W;
    int *CNT;
    cudaGetSymbolAddress((void**)&REPS, g_REPS);
    cudaGetSymbolAddress((void**)&RH,   g_RH);
    cudaGetSymbolAddress((void**)&RL,   g_RL);
    cudaGetSymbolAddress((void**)&XH,   g_XH);
    cudaGetSymbolAddress((void**)&XL,   g_XL);
    cudaGetSymbolAddress((void**)&AGGH, g_AGGH);
    cudaGetSymbolAddress((void**)&AGGL, g_AGGL);
    cudaGetSymbolAddress((void**)&TMPH, g_TMPH);
    cudaGetSymbolAddress((void**)&TMPL, g_TMPL);
    cudaGetSymbolAddress((void**)&W,    g_W);
    cudaGetSymbolAddress((void**)&CNT,  g_cnt);

    cudaFuncSetAttribute(k_mgemm<0>, cudaFuncAttributeMaxDynamicSharedMemorySize, DSMEM);
    cudaFuncSetAttribute(k_mgemm<1>, cudaFuncAttributeMaxDynamicSharedMemorySize, DSMEM);
    cudaFuncSetAttribute(k_mgemm<2>, cudaFuncAttributeMaxDynamicSharedMemorySize, DSMEM);

    const int* src = ei;
    const int* dst = ei + E;

    const int G = (M + 127) / 128;
    const int warp_grid = (M + 7) / 8;

    // ---- prep + CSR ----
    cudaMemsetAsync(CNT, 0, (size_t)M * sizeof(int), 0);
    k_wsplit_all<<<(270336 + 255) / 256, 256>>>(emb_W, lin_l_W, lin_r_W, fus_W1, fus_W2);
    k_count<<<(E + 255) / 256, 256>>>(dst, E);
    k_xsplit<<<((M * 80) + 255) / 256, 256>>>(x, M);

    // ---- embedding: relu(x@W+b) -> REPS slice0 + RH/RL slice0 ----
    {
        ChunkTab ct; ct.nk = 0;
        add_seg(ct, XH, KX, W + W_EMB_HI, KX, 5);
        add_seg(ct, XH, KX, W + W_EMB_LO, KX, 5);
        add_seg(ct, XL, KX, W + W_EMB_HI, KX, 5);
        k_mgemm<1><<<G, 256, DSMEM>>>(ct, emb_b, nullptr, nullptr, nullptr,
                                      REPS, LD, RH, RL, LD, M);
    }

    k_scan<<<1, 1024>>>(M);
    k_fill<<<(E + 255) / 256, 256>>>(src, dst, E);

    // ---- layers ----
    for (int i = 0; i < NL; i++) {
        k_agg<<<warp_grid, 256>>>(REPS + (size_t)i * HID, M);
        ChunkTab ct; ct.nk = 0;
        const __nv_bfloat16* LLH = W + W_LINL(i);
        const __nv_bfloat16* LLL = LLH + 16384;
        const __nv_bfloat16* LRH = W + W_LINR(i);
        const __nv_bfloat16* LRL = LRH + 16384;
        const __nv_bfloat16* HHi = RH + (size_t)i * HID;
        const __nv_bfloat16* HLo = RL + (size_t)i * HID;
        add_seg(ct, AGGH, HID, LLH, HID, 2);
        add_seg(ct, AGGH, HID, LLL, HID, 2);
        add_seg(ct, AGGL, HID, LLH, HID, 2);
        add_seg(ct, HHi,  LD,  LRH, HID, 2);
        add_seg(ct, HHi,  LD,  LRL, HID, 2);
        add_seg(ct, HLo,  LD,  LRH, HID, 2);
        k_mgemm<2><<<G, 256, DSMEM>>>(ct, lin_l_b + (size_t)i * HID,
                                      ln_g + (size_t)i * HID, ln_b + (size_t)i * HID,
                                      (i > 0) ? (REPS + (size_t)i * HID) : nullptr,
                                      (i + 1 < NL) ? (REPS + (size_t)(i + 1) * HID) : nullptr, LD,
                                      RH + (size_t)(i + 1) * HID, RL + (size_t)(i + 1) * HID, LD, M);
    }

    // ---- fusion MLP ----
    {
        ChunkTab ct; ct.nk = 0;
        add_seg(ct, RH, LD, W + W_FUS1_HI, LD, 10);
        add_seg(ct, RH, LD, W + W_FUS1_LO, LD, 10);
        add_seg(ct, RL, LD, W + W_FUS1_HI, LD, 10);
        k_mgemm<1><<<G, 256, DSMEM>>>(ct, fus_b1, nullptr, nullptr, nullptr,
                                      nullptr, 0, TMPH, TMPL, HID, M);
    }
    {
        ChunkTab ct; ct.nk = 0;
        add_seg(ct, TMPH, HID, W + W_FUS2_HI, HID, 2);
        add_seg(ct, TMPH, HID, W + W_FUS2_LO, HID, 2);
        add_seg(ct, TMPL, HID, W + W_FUS2_HI, HID, 2);
        k_mgemm<0><<<G, 256, DSMEM>>>(ct, fus_b2, nullptr, nullptr, nullptr,
                                      out, HID, nullptr, nullptr, 0, M);
    }
}

// round 10
// speedup vs baseline: 1.2366x; 1.0505x over previous
#include <cuda_runtime.h>
#include <cuda_bf16.h>
#include <cstdint>
#include <math.h>

#define NN    50000
#define EE    800000
#define INDIM 300
#define HID   128
#define NL    4
#define LD    640        // (NL+1)*HID reps row
#define KX    320        // padded x width (bf16 hi/lo arrays)

// weight pack offsets (elements) — hi/lo arrays per matrix, [128][Kp] row-major
#define W_EMB_HI 0
#define W_EMB_LO 40960
#define W_LINL(i) (81920  + (i) * 32768)   // lo at +16384
#define W_LINR(i) (212992 + (i) * 32768)   // lo at +16384
#define W_FUS1_HI 344064
#define W_FUS1_LO 425984
#define W_FUS2_HI 507904
#define W_FUS2_LO 524288
#define W_TOTAL   540672

#define DSMEM (1024 + 98304)
#define MAXCH 30

// ---------------- scratch ----------------
__device__ __align__(256) float          g_REPS[(size_t)NN * LD];   // fp32 skip slices 1..3
__device__ __align__(256) __nv_bfloat16  g_RH  [(size_t)NN * LD];   // activation hi, ld 640 (agg + GEMM A)
__device__ __align__(256) __nv_bfloat16  g_RL  [(size_t)NN * LD];   // activation lo, ld 640
__device__ __align__(256) __nv_bfloat16  g_XH  [(size_t)NN * KX];
__device__ __align__(256) __nv_bfloat16  g_XL  [(size_t)NN * KX];
__device__ __align__(256) __nv_bfloat16  g_AGGH[(size_t)NN * HID];
__device__ __align__(256) __nv_bfloat16  g_AGGL[(size_t)NN * HID];
__device__ __align__(256) __nv_bfloat16  g_TMPH[(size_t)NN * HID];
__device__ __align__(256) __nv_bfloat16  g_TMPL[(size_t)NN * HID];
__device__ __align__(256) __nv_bfloat16  g_W   [W_TOTAL];
__device__ float g_invdeg[NN];
__device__ int   g_cnt[NN];
__device__ int   g_cursor[NN];
__device__ int   g_rowptr[NN + 1];
__device__ int   g_col[EE];

// per-chunk pointer table, built on host, passed by value (constant bank)
struct ChunkTab {
    const __nv_bfloat16* A[MAXCH];   // pre-offset by k0
    const __nv_bfloat16* B[MAXCH];   // pre-offset by k0
    int lda[MAXCH];
    int ldb[MAXCH];
    int nk;
};

// ---------------- helpers ----------------
__device__ __forceinline__ uint32_t smem_u32(const void* p) {
    uint32_t a;
    asm("{ .reg .u64 t; cvta.to.shared.u64 t, %1; cvt.u32.u64 %0, t; }" : "=r"(a) : "l"(p));
    return a;
}
#define SW128(b) ((b) ^ (((b) >> 3) & 0x70))

__device__ __forceinline__ void cp16(uint32_t dst, const void* src, int sz) {
    asm volatile("cp.async.cg.shared.global [%0], [%1], 16, %2;"
                 :: "r"(dst), "l"(src), "r"(sz) : "memory");
}
__device__ __forceinline__ void ldm_x4(uint32_t* r, uint32_t addr) {
    asm volatile("ldmatrix.sync.aligned.m8n8.x4.shared.b16 {%0,%1,%2,%3}, [%4];"
                 : "=r"(r[0]), "=r"(r[1]), "=r"(r[2]), "=r"(r[3]) : "r"(addr));
}
__device__ __forceinline__ void mma_bf16(float* c, const uint32_t* a, const uint32_t* b) {
    asm volatile(
        "mma.sync.aligned.m16n8k16.row.col.f32.bf16.bf16.f32 "
        "{%0,%1,%2,%3}, {%4,%5,%6,%7}, {%8,%9}, {%0,%1,%2,%3};"
        : "+f"(c[0]), "+f"(c[1]), "+f"(c[2]), "+f"(c[3])
        : "r"(a[0]), "r"(a[1]), "r"(a[2]), "r"(a[3]), "r"(b[0]), "r"(b[1]));
}
__device__ __forceinline__ void split2(float v, __nv_bfloat16& hi, __nv_bfloat16& lo) {
    hi = __float2bfloat16(v);
    lo = __float2bfloat16(v - __bfloat162float(hi));
}

// ---------------- CSR build ----------------
__global__ void k_count(const int* __restrict__ dst, int E) {
    int i = blockIdx.x * blockDim.x + threadIdx.x;
    if (i < E) atomicAdd(&g_cnt[dst[i]], 1);
}

__global__ void __launch_bounds__(1024) k_scan(int M) {
    const int T = 1024;
    int t = threadIdx.x;
    int per = (M + T - 1) / T;
    int beg = t * per;
    int end = min(beg + per, M);
    int sum = 0;
    for (int i = beg; i < end; i++) sum += g_cnt[i];

    int lane = t & 31, wid = t >> 5;
    int v = sum;
    #pragma unroll
    for (int o = 1; o < 32; o <<= 1) {
        int u = __shfl_up_sync(0xffffffffu, v, o);
        if (lane >= o) v += u;
    }
    __shared__ int ws[32];
    if (lane == 31) ws[wid] = v;
    __syncthreads();
    if (wid == 0) {
        int wv = ws[lane];
        #pragma unroll
        for (int o = 1; o < 32; o <<= 1) {
            int u = __shfl_up_sync(0xffffffffu, wv, o);
            if (lane >= o) wv += u;
        }
        ws[lane] = wv;
    }
    __syncthreads();
    int run = v - sum + (wid ? ws[wid - 1] : 0);
    for (int i = beg; i < end; i++) {
        int c = g_cnt[i];
        g_rowptr[i] = run;
        g_cursor[i] = run;
        g_invdeg[i] = 1.0f / fmaxf((float)c, 1.0f);
        run += c;
    }
    if (t == T - 1) g_rowptr[M] = run;
}

__global__ void k_fill(const int* __restrict__ src, const int* __restrict__ dst, int E) {
    int i = blockIdx.x * blockDim.x + threadIdx.x;
    if (i < E) {
        int pos = atomicAdd(&g_cursor[dst[i]], 1);
        g_col[pos] = src[i];
    }
}

// ---------------- weight prep (one launch; writes hi+lo arrays) ----------------
__device__ __forceinline__ void wsplit_one(const float* W, __nv_bfloat16* ohi,
                                           __nv_bfloat16* olo, int idx, int K, int Kp) {
    int n = idx / Kp, kp = idx % Kp;
    __nv_bfloat16 hi, lo;
    if (kp < K) {
        split2(W[(size_t)kp * 128 + n], hi, lo);
    } else {
        hi = __float2bfloat16(0.f); lo = hi;
    }
    ohi[(size_t)n * Kp + kp] = hi;
    olo[(size_t)n * Kp + kp] = lo;
}

__global__ void k_wsplit_all(const float* __restrict__ emb_W,
                             const float* __restrict__ lin_l_W,
                             const float* __restrict__ lin_r_W,
                             const float* __restrict__ fus_W1,
                             const float* __restrict__ fus_W2) {
    int w = blockIdx.x * blockDim.x + threadIdx.x;
    if (w < 40960) {
        wsplit_one(emb_W, g_W + W_EMB_HI, g_W + W_EMB_LO, w, 300, 320);
    } else if (w < 106496) {
        int u = w - 40960, i = u >> 14;
        wsplit_one(lin_l_W + (size_t)i * 16384, g_W + W_LINL(i), g_W + W_LINL(i) + 16384,
                   u & 16383, 128, 128);
    } else if (w < 172032) {
        int u = w - 106496, i = u >> 14;
        wsplit_one(lin_r_W + (size_t)i * 16384, g_W + W_LINR(i), g_W + W_LINR(i) + 16384,
                   u & 16383, 128, 128);
    } else if (w < 253952) {
        wsplit_one(fus_W1, g_W + W_FUS1_HI, g_W + W_FUS1_LO, w - 172032, 640, 640);
    } else if (w < 270336) {
        wsplit_one(fus_W2, g_W + W_FUS2_HI, g_W + W_FUS2_LO, w - 253952, 128, 128);
    }
}

// x [M,300] fp32 -> XH/XL [M,320] bf16, zero pad
__global__ void k_xsplit(const float* __restrict__ x, int M) {
    int idx = blockIdx.x * blockDim.x + threadIdx.x;
    int row = idx / 80, g = idx % 80;
    if (row >= M) return;
    float vv[4] = {0.f, 0.f, 0.f, 0.f};
    if (g < 75) {
        float4 t = *reinterpret_cast<const float4*>(x + (size_t)row * INDIM + g * 4);
        vv[0] = t.x; vv[1] = t.y; vv[2] = t.z; vv[3] = t.w;
    }
    union { __nv_bfloat16 h[4]; uint2 u; } ph, pl;
    #pragma unroll
    for (int j = 0; j < 4; j++) split2(vv[j], ph.h[j], pl.h[j]);
    *reinterpret_cast<uint2*>(g_XH + (size_t)row * KX + g * 4) = ph.u;
    *reinterpret_cast<uint2*>(g_XL + (size_t)row * KX + g * 4) = pl.u;
}

// ---------------- mean aggregation from bf16-hi rows -> hi/lo bf16 ----------------
__global__ void k_agg(const __nv_bfloat16* __restrict__ H /* RH slice, ld=LD */, int M) {
    int gw   = (blockIdx.x * blockDim.x + threadIdx.x) >> 5;
    int lane = threadIdx.x & 31;
    if (gw >= M) return;
    int beg = g_rowptr[gw], end = g_rowptr[gw + 1];
    float a0 = 0.f, a1 = 0.f, a2 = 0.f, a3 = 0.f;
    float b0 = 0.f, b1 = 0.f, b2 = 0.f, b3 = 0.f;
    union U { uint2 u; __nv_bfloat162 h2[2]; };
    for (int base = beg; base < end; base += 32) {
        int idx = (base + lane < end) ? g_col[base + lane] : 0;
        int cnt = min(32, end - base);
        int j = 0;
        for (; j + 3 < cnt; j += 4) {
            int s0 = __shfl_sync(0xffffffffu, idx, j);
            int s1 = __shfl_sync(0xffffffffu, idx, j + 1);
            int s2 = __shfl_sync(0xffffffffu, idx, j + 2);
            int s3 = __shfl_sync(0xffffffffu, idx, j + 3);
            U u0, u1, u2, u3;
            u0.u = *reinterpret_cast<const uint2*>(H + (size_t)s0 * LD + lane * 4);
            u1.u = *reinterpret_cast<const uint2*>(H + (size_t)s1 * LD + lane * 4);
            u2.u = *reinterpret_cast<const uint2*>(H + (size_t)s2 * LD + lane * 4);
            u3.u = *reinterpret_cast<const uint2*>(H + (size_t)s3 * LD + lane * 4);
            float2 p;
            p = __bfloat1622float2(u0.h2[0]); a0 += p.x; a1 += p.y;
            p = __bfloat1622float2(u0.h2[1]); a2 += p.x; a3 += p.y;
            p = __bfloat1622float2(u1.h2[0]); b0 += p.x; b1 += p.y;
            p = __bfloat1622float2(u1.h2[1]); b2 += p.x; b3 += p.y;
            p = __bfloat1622float2(u2.h2[0]); a0 += p.x; a1 += p.y;
            p = __bfloat1622float2(u2.h2[1]); a2 += p.x; a3 += p.y;
            p = __bfloat1622float2(u3.h2[0]); b0 += p.x; b1 += p.y;
            p = __bfloat1622float2(u3.h2[1]); b2 += p.x; b3 += p.y;
        }
        for (; j < cnt; j++) {
            int s = __shfl_sync(0xffffffffu, idx, j);
            U u; u.u = *reinterpret_cast<const uint2*>(H + (size_t)s * LD + lane * 4);
            float2 p;
            p = __bfloat1622float2(u.h2[0]); a0 += p.x; a1 += p.y;
            p = __bfloat1622float2(u.h2[1]); a2 += p.x; a3 += p.y;
        }
    }
    a0 += b0; a1 += b1; a2 += b2; a3 += b3;
    float w = g_invdeg[gw];
    float m[4] = {a0 * w, a1 * w, a2 * w, a3 * w};
    union { __nv_bfloat16 h[4]; uint2 u; } ph, pl;
    #pragma unroll
    for (int j = 0; j < 4; j++) split2(m[j], ph.h[j], pl.h[j]);
    *reinterpret_cast<uint2*>(g_AGGH + (size_t)gw * HID + lane * 4) = ph.u;
    *reinterpret_cast<uint2*>(g_AGGL + (size_t)gw * HID + lane * 4) = pl.u;
}

// ---------------- tile loader (32-bit address math) ----------------
__device__ __forceinline__ void load_tiles(uint32_t tiles, int s, int tid, int m0, int M,
                                           const __nv_bfloat16* A, int lda,
                                           const __nv_bfloat16* B, int ldb) {
    uint32_t abase = tiles + (uint32_t)s * 32768u;
    uint32_t bbase = abase + 16384u;
    #pragma unroll
    for (int i = 0; i < 4; i++) {
        int v = tid + i * 256;
        int r = v >> 3, ch = v & 7;
        uint32_t bo = (uint32_t)(r * 128 + ch * 16);
        int row = m0 + r;
        int rc = row < M ? row : 0;
        cp16(abase + SW128(bo), A + (rc * lda + ch * 8), row < M ? 16 : 0);
    }
    #pragma unroll
    for (int i = 0; i < 4; i++) {
        int v = tid + i * 256;
        int r = v >> 3, ch = v & 7;
        uint32_t bo = (uint32_t)(r * 128 + ch * 16);
        cp16(bbase + SW128(bo), B + (r * ldb + ch * 8), 16);
    }
    asm volatile("cp.async.commit_group;" ::: "memory");
}

// ---------------- mma.sync GEMM, 128x128 tile, BK=64, 3-stage, chunk table ----------------
// MODE 0: C + bias                              -> outF
// MODE 1: relu(C + bias)                        -> [outF] + (outH,outL)
// MODE 2: LN(C + bias)*g+b (+skip), relu        -> [outF] + (outH,outL)
template <int MODE>
__global__ void __launch_bounds__(256, 2)
k_mgemm(ChunkTab ct,
        const float* __restrict__ bias, const float* __restrict__ lng, const float* __restrict__ lnb,
        const float* __restrict__ skip, float* __restrict__ outF, int ldF,
        __nv_bfloat16* __restrict__ outH, __nv_bfloat16* __restrict__ outL, int ldo, int M) {
    extern __shared__ char smem_raw[];
    char* smem = (char*)(((uintptr_t)smem_raw + 1023) & ~(uintptr_t)1023);
    const uint32_t tiles = smem_u32(smem);

    const int tid  = threadIdx.x;
    const int lane = tid & 31, wid = tid >> 5;
    const int m0   = blockIdx.x * 128;

    const int wm = (wid & 1) * 64;
    const int wn = (wid >> 1) * 32;

    float acc[4][4][4];
    #pragma unroll
    for (int i = 0; i < 4; i++)
        #pragma unroll
        for (int j = 0; j < 4; j++)
            #pragma unroll
            for (int q = 0; q < 4; q++) acc[i][j][q] = 0.f;

    const int nk = ct.nk;

    // A ldmatrix lane addressing
    const int r_in = ((lane >> 3) & 1) * 8 + (lane & 7);
    const int ca8  = (lane >> 4) * 8;
    // B ldmatrix x4 (two n8 slices per load): g = lane>>3, r = lane&7
    const int bg   = lane >> 3;
    const int brow = lane & 7;
    const int b_na_off  = (bg >> 1) * 8;     // 0 or 8 within the na-pair
    const int b_kslice  = (bg & 1) * 8;      // 0 or 8 within ka*16

    load_tiles(tiles, 0, tid, m0, M, ct.A[0], ct.lda[0], ct.B[0], ct.ldb[0]);
    if (nk > 1) load_tiles(tiles, 1, tid, m0, M, ct.A[1], ct.lda[1], ct.B[1], ct.ldb[1]);

    #pragma unroll 1
    for (int c = 0; c < nk; c++) {
        if (c + 1 < nk) asm volatile("cp.async.wait_group 1;" ::: "memory");
        else            asm volatile("cp.async.wait_group 0;" ::: "memory");
        __syncthreads();
        if (c + 2 < nk) {
            int cn = c + 2;
            load_tiles(tiles, cn % 3, tid, m0, M, ct.A[cn], ct.lda[cn], ct.B[cn], ct.ldb[cn]);
        }

        uint32_t abase = tiles + (uint32_t)(c % 3) * 32768u;
        uint32_t bbase = abase + 16384u;
        #pragma unroll
        for (int ka = 0; ka < 4; ka++) {
            uint32_t a[4][4];
            #pragma unroll
            for (int ma = 0; ma < 4; ma++) {
                int r = wm + ma * 16 + r_in, cc = ka * 16 + ca8;
                ldm_x4(a[ma], abase + SW128((uint32_t)(r * 128 + cc * 2)));
            }
            uint32_t b[2][4];   // b[na2] = {na0 klo, na0 khi, na1 klo, na1 khi}
            #pragma unroll
            for (int na2 = 0; na2 < 2; na2++) {
                int r  = wn + na2 * 16 + b_na_off + brow;
                int cc = ka * 16 + b_kslice;
                ldm_x4(b[na2], bbase + SW128((uint32_t)(r * 128 + cc * 2)));
            }
            #pragma unroll
            for (int ma = 0; ma < 4; ma++)
                #pragma unroll
                for (int na = 0; na < 4; na++)
                    mma_bf16(acc[ma][na], a[ma], &b[na >> 1][(na & 1) * 2]);
        }
    }
    __syncthreads();

    // park accumulators in smem C [128][132] fp32
    float* C = (float*)smem;
    #pragma unroll
    for (int ma = 0; ma < 4; ma++)
        #pragma unroll
        for (int na = 0; na < 4; na++) {
            int r0 = wm + ma * 16 + (lane >> 2);
            int cc = wn + na * 8 + 2 * (lane & 3);
            C[r0 * 132 + cc]           = acc[ma][na][0];
            C[r0 * 132 + cc + 1]       = acc[ma][na][1];
            C[(r0 + 8) * 132 + cc]     = acc[ma][na][2];
            C[(r0 + 8) * 132 + cc + 1] = acc[ma][na][3];
        }
    __syncthreads();

    // epilogue: warp per row
    #pragma unroll 1
    for (int t = 0; t < 16; t++) {
        int rr  = wid + t * 8;
        int row = m0 + rr;
        if (row >= M) continue;
        float4 v = *reinterpret_cast<float4*>(C + rr * 132 + lane * 4);
        float4 bb = *reinterpret_cast<const float4*>(bias + lane * 4);
        v.x += bb.x; v.y += bb.y; v.z += bb.z; v.w += bb.w;
        if (MODE == 2) {
            float s  = v.x + v.y + v.z + v.w;
            float ss = v.x * v.x + v.y * v.y + v.z * v.z + v.w * v.w;
            #pragma unroll
            for (int off = 16; off; off >>= 1) {
                s  += __shfl_xor_sync(0xffffffffu, s,  off);
                ss += __shfl_xor_sync(0xffffffffu, ss, off);
            }
            float mu  = s * (1.0f / 128.0f);
            float var = ss * (1.0f / 128.0f) - mu * mu;
            float inv = rsqrtf(var + 1e-5f);
            float4 gg = *reinterpret_cast<const float4*>(lng + lane * 4);
            float4 ob = *reinterpret_cast<const float4*>(lnb + lane * 4);
            v.x = (v.x - mu) * inv * gg.x + ob.x;
            v.y = (v.y - mu) * inv * gg.y + ob.y;
            v.z = (v.z - mu) * inv * gg.z + ob.z;
            v.w = (v.w - mu) * inv * gg.w + ob.w;
            if (skip) {
                float4 sk = *reinterpret_cast<const float4*>(skip + (size_t)row * LD + lane * 4);
                v.x += sk.x; v.y += sk.y; v.z += sk.z; v.w += sk.w;
            }
        }
        if (MODE != 0) {
            v.x = fmaxf(v.x, 0.f); v.y = fmaxf(v.y, 0.f);
            v.z = fmaxf(v.z, 0.f); v.w = fmaxf(v.w, 0.f);
        }
        if (outF) {
            *reinterpret_cast<float4*>(outF + (size_t)row * ldF + lane * 4) = v;
        }
        if (MODE != 0) {
            union { __nv_bfloat16 h[4]; uint2 u; } ph, pl;
            float vv[4] = {v.x, v.y, v.z, v.w};
            #pragma unroll
            for (int jj = 0; jj < 4; jj++) split2(vv[jj], ph.h[jj], pl.h[jj]);
            *reinterpret_cast<uint2*>(outH + (size_t)row * ldo + lane * 4) = ph.u;
            *reinterpret_cast<uint2*>(outL + (size_t)row * ldo + lane * 4) = pl.u;
        }
    }
}

// host-side chunk table builder: append one segment (nch chunks of K=64)
static inline void add_seg(ChunkTab& ct, const __nv_bfloat16* A, int lda,
                           const __nv_bfloat16* B, int ldb, int nch) {
    for (int c = 0; c < nch; c++) {
        ct.A[ct.nk]   = A + c * 64;
        ct.B[ct.nk]   = B + c * 64;
        ct.lda[ct.nk] = lda;
        ct.ldb[ct.nk] = ldb;
        ct.nk++;
    }
}

// ---------------- launch ----------------
extern "C" void kernel_launch(void* const* d_in, const int* in_sizes, int n_in,
                              void* d_out, int out_size) {
    const float* x       = (const float*)d_in[0];
    const int*   ei      = (const int*)  d_in[1];
    const float* emb_W   = (const float*)d_in[2];
    const float* emb_b   = (const float*)d_in[3];
    const float* lin_l_W = (const float*)d_in[4];
    const float* lin_l_b = (const float*)d_in[5];
    const float* lin_r_W = (const float*)d_in[6];
    const float* ln_g    = (const float*)d_in[7];
    const float* ln_b    = (const float*)d_in[8];
    const float* fus_W1  = (const float*)d_in[9];
    const float* fus_b1  = (const float*)d_in[10];
    const float* fus_W2  = (const float*)d_in[11];
    const float* fus_b2  = (const float*)d_in[12];
    float* out = (float*)d_out;

    const int M = in_sizes[0] / INDIM;
    const int E = in_sizes[1] / 2;

    float *REPS; __nv_bfloat16 *RH, *RL, *XH, *XL, *AGGH, *AGGL, *TMPH, *TMPL, *W;
    int *CNT;
    cudaGetSymbolAddress((void**)&REPS, g_REPS);
    cudaGetSymbolAddress((void**)&RH,   g_RH);
    cudaGetSymbolAddress((void**)&RL,   g_RL);
    cudaGetSymbolAddress((void**)&XH,   g_XH);
    cudaGetSymbolAddress((void**)&XL,   g_XL);
    cudaGetSymbolAddress((void**)&AGGH, g_AGGH);
    cudaGetSymbolAddress((void**)&AGGL, g_AGGL);
    cudaGetSymbolAddress((void**)&TMPH, g_TMPH);
    cudaGetSymbolAddress((void**)&TMPL, g_TMPL);
    cudaGetSymbolAddress((void**)&W,    g_W);
    cudaGetSymbolAddress((void**)&CNT,  g_cnt);

    cudaFuncSetAttribute(k_mgemm<0>, cudaFuncAttributeMaxDynamicSharedMemorySize, DSMEM);
    cudaFuncSetAttribute(k_mgemm<1>, cudaFuncAttributeMaxDynamicSharedMemorySize, DSMEM);
    cudaFuncSetAttribute(k_mgemm<2>, cudaFuncAttributeMaxDynamicSharedMemorySize, DSMEM);

    const int* src = ei;
    const int* dst = ei + E;

    const int G = (M + 127) / 128;
    const int warp_grid = (M + 7) / 8;

    // ---- prep + CSR ----
    cudaMemsetAsync(CNT, 0, (size_t)M * sizeof(int), 0);
    k_wsplit_all<<<(270336 + 255) / 256, 256>>>(emb_W, lin_l_W, lin_r_W, fus_W1, fus_W2);
    k_count<<<(E + 255) / 256, 256>>>(dst, E);
    k_xsplit<<<((M * 80) + 255) / 256, 256>>>(x, M);

    // ---- embedding: relu(x@W+b) -> RH/RL slice0 (no fp32 out; agg reads RH) ----
    {
        ChunkTab ct; ct.nk = 0;
        add_seg(ct, XH, KX, W + W_EMB_HI, KX, 5);
        add_seg(ct, XH, KX, W + W_EMB_LO, KX, 5);
        add_seg(ct, XL, KX, W + W_EMB_HI, KX, 5);
        k_mgemm<1><<<G, 256, DSMEM>>>(ct, emb_b, nullptr, nullptr, nullptr,
                                      nullptr, 0, RH, RL, LD, M);
    }

    k_scan<<<1, 1024>>>(M);
    k_fill<<<(E + 255) / 256, 256>>>(src, dst, E);

    // ---- layers ----
    for (int i = 0; i < NL; i++) {
        k_agg<<<warp_grid, 256>>>(RH + (size_t)i * HID, M);
        ChunkTab ct; ct.nk = 0;
        const __nv_bfloat16* LLH = W + W_LINL(i);
        const __nv_bfloat16* LLL = LLH + 16384;
        const __nv_bfloat16* LRH = W + W_LINR(i);
        const __nv_bfloat16* LRL = LRH + 16384;
        const __nv_bfloat16* HHi = RH + (size_t)i * HID;
        const __nv_bfloat16* HLo = RL + (size_t)i * HID;
        add_seg(ct, AGGH, HID, LLH, HID, 2);
        add_seg(ct, AGGH, HID, LLL, HID, 2);
        add_seg(ct, AGGL, HID, LLH, HID, 2);
        add_seg(ct, HHi,  LD,  LRH, HID, 2);
        add_seg(ct, HHi,  LD,  LRL, HID, 2);
        add_seg(ct, HLo,  LD,  LRH, HID, 2);
        k_mgemm<2><<<G, 256, DSMEM>>>(ct, lin_l_b + (size_t)i * HID,
                                      ln_g + (size_t)i * HID, ln_b + (size_t)i * HID,
                                      (i > 0) ? (REPS + (size_t)i * HID) : nullptr,
                                      (i + 1 < NL) ? (REPS + (size_t)(i + 1) * HID) : nullptr, LD,
                                      RH + (size_t)(i + 1) * HID, RL + (size_t)(i + 1) * HID, LD, M);
    }

    // ---- fusion MLP ----
    {
        ChunkTab ct; ct.nk = 0;
        add_seg(ct, RH, LD, W + W_FUS1_HI, LD, 10);
        add_seg(ct, RH, LD, W + W_FUS1_LO, LD, 10);
        add_seg(ct, RL, LD, W + W_FUS1_HI, LD, 10);
        k_mgemm<1><<<G, 256, DSMEM>>>(ct, fus_b1, nullptr, nullptr, nullptr,
                                      nullptr, 0, TMPH, TMPL, HID, M);
    }
    {
        ChunkTab ct; ct.nk = 0;
        add_seg(ct, TMPH, HID, W + W_FUS2_HI, HID, 2);
        add_seg(ct, TMPH, HID, W + W_FUS2_LO, HID, 2);
        add_seg(ct, TMPL, HID, W + W_FUS2_HI, HID, 2);
        k_mgemm<0><<<G, 256, DSMEM>>>(ct, fus_b2, nullptr, nullptr, nullptr,
                                      out, HID, nullptr, nullptr, 0, M);
    }
}

// round 11
// speedup vs baseline: 1.2722x; 1.0288x over previous
#include <cuda_runtime.h>
#include <cuda_bf16.h>
#include <cstdint>
#include <math.h>

#define NN    50000
#define EE    800000
#define INDIM 300
#define HID   128
#define NL    4
#define LD    640        // (NL+1)*HID reps row
#define KX    320        // padded x width (bf16 hi/lo arrays)

// weight pack offsets (elements) — hi/lo arrays per matrix, [128][Kp] row-major
#define W_EMB_HI 0
#define W_EMB_LO 40960
#define W_LINL(i) (81920  + (i) * 32768)   // lo at +16384
#define W_LINR(i) (212992 + (i) * 32768)   // lo at +16384
#define W_FUS1_HI 344064
#define W_FUS1_LO 425984
#define W_FUS2_HI 507904
#define W_FUS2_LO 524288
#define W_TOTAL   540672

// BM=64, BN=128: stage = A(8KB) + B(16KB) = 24KB, 3 stages = 72KB
#define STAGE_SZ 24576
#define DSMEM (1024 + 3 * STAGE_SZ)
#define MAXCH 30

// ---------------- scratch ----------------
__device__ __align__(256) float          g_REPS[(size_t)NN * LD];   // fp32 skip slices 1..3
__device__ __align__(256) __nv_bfloat16  g_RH  [(size_t)NN * LD];   // activation hi (agg + GEMM A)
__device__ __align__(256) __nv_bfloat16  g_RL  [(size_t)NN * LD];   // activation lo
__device__ __align__(256) __nv_bfloat16  g_XH  [(size_t)NN * KX];
__device__ __align__(256) __nv_bfloat16  g_XL  [(size_t)NN * KX];
__device__ __align__(256) __nv_bfloat16  g_AGGH[(size_t)NN * HID];
__device__ __align__(256) __nv_bfloat16  g_AGGL[(size_t)NN * HID];
__device__ __align__(256) __nv_bfloat16  g_TMPH[(size_t)NN * HID];
__device__ __align__(256) __nv_bfloat16  g_TMPL[(size_t)NN * HID];
__device__ __align__(256) __nv_bfloat16  g_W   [W_TOTAL];
__device__ float g_invdeg[NN];
__device__ int   g_cnt[NN];
__device__ int   g_cursor[NN];
__device__ int   g_rowptr[NN + 1];
__device__ int   g_col[EE];

// per-chunk pointer table, built on host, passed by value (constant bank)
struct ChunkTab {
    const __nv_bfloat16* A[MAXCH];   // pre-offset by k0
    const __nv_bfloat16* B[MAXCH];   // pre-offset by k0
    int lda[MAXCH];
    int ldb[MAXCH];
    int nk;
};

// ---------------- helpers ----------------
__device__ __forceinline__ uint32_t smem_u32(const void* p) {
    uint32_t a;
    asm("{ .reg .u64 t; cvta.to.shared.u64 t, %1; cvt.u32.u64 %0, t; }" : "=r"(a) : "l"(p));
    return a;
}
#define SW128(b) ((b) ^ (((b) >> 3) & 0x70))

__device__ __forceinline__ void cp16(uint32_t dst, const void* src, int sz) {
    asm volatile("cp.async.cg.shared.global [%0], [%1], 16, %2;"
                 :: "r"(dst), "l"(src), "r"(sz) : "memory");
}
__device__ __forceinline__ void ldm_x4(uint32_t* r, uint32_t addr) {
    asm volatile("ldmatrix.sync.aligned.m8n8.x4.shared.b16 {%0,%1,%2,%3}, [%4];"
                 : "=r"(r[0]), "=r"(r[1]), "=r"(r[2]), "=r"(r[3]) : "r"(addr));
}
__device__ __forceinline__ void mma_bf16(float* c, const uint32_t* a, const uint32_t* b) {
    asm volatile(
        "mma.sync.aligned.m16n8k16.row.col.f32.bf16.bf16.f32 "
        "{%0,%1,%2,%3}, {%4,%5,%6,%7}, {%8,%9}, {%0,%1,%2,%3};"
        : "+f"(c[0]), "+f"(c[1]), "+f"(c[2]), "+f"(c[3])
        : "r"(a[0]), "r"(a[1]), "r"(a[2]), "r"(a[3]), "r"(b[0]), "r"(b[1]));
}
__device__ __forceinline__ void split2(float v, __nv_bfloat16& hi, __nv_bfloat16& lo) {
    hi = __float2bfloat16(v);
    lo = __float2bfloat16(v - __bfloat162float(hi));
}

// ---------------- CSR build ----------------
__global__ void k_count(const int* __restrict__ dst, int E) {
    int i = blockIdx.x * blockDim.x + threadIdx.x;
    if (i < E) atomicAdd(&g_cnt[dst[i]], 1);
}

__global__ void __launch_bounds__(1024) k_scan(int M) {
    const int T = 1024;
    int t = threadIdx.x;
    int per = (M + T - 1) / T;
    int beg = t * per;
    int end = min(beg + per, M);
    int sum = 0;
    for (int i = beg; i < end; i++) sum += g_cnt[i];

    int lane = t & 31, wid = t >> 5;
    int v = sum;
    #pragma unroll
    for (int o = 1; o < 32; o <<= 1) {
        int u = __shfl_up_sync(0xffffffffu, v, o);
        if (lane >= o) v += u;
    }
    __shared__ int ws[32];
    if (lane == 31) ws[wid] = v;
    __syncthreads();
    if (wid == 0) {
        int wv = ws[lane];
        #pragma unroll
        for (int o = 1; o < 32; o <<= 1) {
            int u = __shfl_up_sync(0xffffffffu, wv, o);
            if (lane >= o) wv += u;
        }
        ws[lane] = wv;
    }
    __syncthreads();
    int run = v - sum + (wid ? ws[wid - 1] : 0);
    for (int i = beg; i < end; i++) {
        int c = g_cnt[i];
        g_rowptr[i] = run;
        g_cursor[i] = run;
        g_invdeg[i] = 1.0f / fmaxf((float)c, 1.0f);
        run += c;
    }
    if (t == T - 1) g_rowptr[M] = run;
}

__global__ void k_fill(const int* __restrict__ src, const int* __restrict__ dst, int E) {
    int i = blockIdx.x * blockDim.x + threadIdx.x;
    if (i < E) {
        int pos = atomicAdd(&g_cursor[dst[i]], 1);
        g_col[pos] = src[i];
    }
}

// ---------------- weight prep (one launch; writes hi+lo arrays) ----------------
__device__ __forceinline__ void wsplit_one(const float* W, __nv_bfloat16* ohi,
                                           __nv_bfloat16* olo, int idx, int K, int Kp) {
    int n = idx / Kp, kp = idx % Kp;
    __nv_bfloat16 hi, lo;
    if (kp < K) {
        split2(W[(size_t)kp * 128 + n], hi, lo);
    } else {
        hi = __float2bfloat16(0.f); lo = hi;
    }
    ohi[(size_t)n * Kp + kp] = hi;
    olo[(size_t)n * Kp + kp] = lo;
}

__global__ void k_wsplit_all(const float* __restrict__ emb_W,
                             const float* __restrict__ lin_l_W,
                             const float* __restrict__ lin_r_W,
                             const float* __restrict__ fus_W1,
                             const float* __restrict__ fus_W2) {
    int w = blockIdx.x * blockDim.x + threadIdx.x;
    if (w < 40960) {
        wsplit_one(emb_W, g_W + W_EMB_HI, g_W + W_EMB_LO, w, 300, 320);
    } else if (w < 106496) {
        int u = w - 40960, i = u >> 14;
        wsplit_one(lin_l_W + (size_t)i * 16384, g_W + W_LINL(i), g_W + W_LINL(i) + 16384,
                   u & 16383, 128, 128);
    } else if (w < 172032) {
        int u = w - 106496, i = u >> 14;
        wsplit_one(lin_r_W + (size_t)i * 16384, g_W + W_LINR(i), g_W + W_LINR(i) + 16384,
                   u & 16383, 128, 128);
    } else if (w < 253952) {
        wsplit_one(fus_W1, g_W + W_FUS1_HI, g_W + W_FUS1_LO, w - 172032, 640, 640);
    } else if (w < 270336) {
        wsplit_one(fus_W2, g_W + W_FUS2_HI, g_W + W_FUS2_LO, w - 253952, 128, 128);
    }
}

// x [M,300] fp32 -> XH/XL [M,320] bf16, zero pad
__global__ void k_xsplit(const float* __restrict__ x, int M) {
    int idx = blockIdx.x * blockDim.x + threadIdx.x;
    int row = idx / 80, g = idx % 80;
    if (row >= M) return;
    float vv[4] = {0.f, 0.f, 0.f, 0.f};
    if (g < 75) {
        float4 t = *reinterpret_cast<const float4*>(x + (size_t)row * INDIM + g * 4);
        vv[0] = t.x; vv[1] = t.y; vv[2] = t.z; vv[3] = t.w;
    }
    union { __nv_bfloat16 h[4]; uint2 u; } ph, pl;
    #pragma unroll
    for (int j = 0; j < 4; j++) split2(vv[j], ph.h[j], pl.h[j]);
    *reinterpret_cast<uint2*>(g_XH + (size_t)row * KX + g * 4) = ph.u;
    *reinterpret_cast<uint2*>(g_XL + (size_t)row * KX + g * 4) = pl.u;
}

// ---------------- mean aggregation from bf16-hi rows -> hi/lo bf16 ----------------
__global__ void k_agg(const __nv_bfloat16* __restrict__ H /* RH slice, ld=LD */, int M) {
    int gw   = (blockIdx.x * blockDim.x + threadIdx.x) >> 5;
    int lane = threadIdx.x & 31;
    if (gw >= M) return;
    int beg = g_rowptr[gw], end = g_rowptr[gw + 1];
    float a0 = 0.f, a1 = 0.f, a2 = 0.f, a3 = 0.f;
    float b0 = 0.f, b1 = 0.f, b2 = 0.f, b3 = 0.f;
    union U { uint2 u; __nv_bfloat162 h2[2]; };
    for (int base = beg; base < end; base += 32) {
        int idx = (base + lane < end) ? g_col[base + lane] : 0;
        int cnt = min(32, end - base);
        int j = 0;
        for (; j + 3 < cnt; j += 4) {
            int s0 = __shfl_sync(0xffffffffu, idx, j);
            int s1 = __shfl_sync(0xffffffffu, idx, j + 1);
            int s2 = __shfl_sync(0xffffffffu, idx, j + 2);
            int s3 = __shfl_sync(0xffffffffu, idx, j + 3);
            U u0, u1, u2, u3;
            u0.u = *reinterpret_cast<const uint2*>(H + (size_t)s0 * LD + lane * 4);
            u1.u = *reinterpret_cast<const uint2*>(H + (size_t)s1 * LD + lane * 4);
            u2.u = *reinterpret_cast<const uint2*>(H + (size_t)s2 * LD + lane * 4);
            u3.u = *reinterpret_cast<const uint2*>(H + (size_t)s3 * LD + lane * 4);
            float2 p;
            p = __bfloat1622float2(u0.h2[0]); a0 += p.x; a1 += p.y;
            p = __bfloat1622float2(u0.h2[1]); a2 += p.x; a3 += p.y;
            p = __bfloat1622float2(u1.h2[0]); b0 += p.x; b1 += p.y;
            p = __bfloat1622float2(u1.h2[1]); b2 += p.x; b3 += p.y;
            p = __bfloat1622float2(u2.h2[0]); a0 += p.x; a1 += p.y;
            p = __bfloat1622float2(u2.h2[1]); a2 += p.x; a3 += p.y;
            p = __bfloat1622float2(u3.h2[0]); b0 += p.x; b1 += p.y;
            p = __bfloat1622float2(u3.h2[1]); b2 += p.x; b3 += p.y;
        }
        for (; j < cnt; j++) {
            int s = __shfl_sync(0xffffffffu, idx, j);
            U u; u.u = *reinterpret_cast<const uint2*>(H + (size_t)s * LD + lane * 4);
            float2 p;
            p = __bfloat1622float2(u.h2[0]); a0 += p.x; a1 += p.y;
            p = __bfloat1622float2(u.h2[1]); a2 += p.x; a3 += p.y;
        }
    }
    a0 += b0; a1 += b1; a2 += b2; a3 += b3;
    float w = g_invdeg[gw];
    float m[4] = {a0 * w, a1 * w, a2 * w, a3 * w};
    union { __nv_bfloat16 h[4]; uint2 u; } ph, pl;
    #pragma unroll
    for (int j = 0; j < 4; j++) split2(m[j], ph.h[j], pl.h[j]);
    *reinterpret_cast<uint2*>(g_AGGH + (size_t)gw * HID + lane * 4) = ph.u;
    *reinterpret_cast<uint2*>(g_AGGL + (size_t)gw * HID + lane * 4) = pl.u;
}

// ---------------- tile loader: A 64x64bf16 (8KB), B 128x64bf16 (16KB) ----------------
__device__ __forceinline__ void load_tiles(uint32_t tiles, int s, int tid, int m0, int M,
                                           const __nv_bfloat16* A, int lda,
                                           const __nv_bfloat16* B, int ldb) {
    uint32_t abase = tiles + (uint32_t)s * STAGE_SZ;
    uint32_t bbase = abase + 8192u;
    // A: 64 rows * 8 chunks = 512 vec16 -> 2 iters
    #pragma unroll
    for (int i = 0; i < 2; i++) {
        int v = tid + i * 256;
        int r = v >> 3, ch = v & 7;
        uint32_t bo = (uint32_t)(r * 128 + ch * 16);
        int row = m0 + r;
        int rc = row < M ? row : 0;
        cp16(abase + SW128(bo), A + (rc * lda + ch * 8), row < M ? 16 : 0);
    }
    // B: 128 rows * 8 chunks = 1024 vec16 -> 4 iters
    #pragma unroll
    for (int i = 0; i < 4; i++) {
        int v = tid + i * 256;
        int r = v >> 3, ch = v & 7;
        uint32_t bo = (uint32_t)(r * 128 + ch * 16);
        cp16(bbase + SW128(bo), B + (r * ldb + ch * 8), 16);
    }
    asm volatile("cp.async.commit_group;" ::: "memory");
}

// ---------------- mma.sync GEMM, 64x128 tile, BK=64, 3-stage, chunk table ----------------
// MODE 0: C + bias                              -> outF
// MODE 1: relu(C + bias)                        -> [outF] + (outH,outL)
// MODE 2: LN(C + bias)*g+b (+skip), relu        -> [outF] + (outH,outL)
template <int MODE>
__global__ void __launch_bounds__(256, 3)
k_mgemm(ChunkTab ct,
        const float* __restrict__ bias, const float* __restrict__ lng, const float* __restrict__ lnb,
        const float* __restrict__ skip, float* __restrict__ outF, int ldF,
        __nv_bfloat16* __restrict__ outH, __nv_bfloat16* __restrict__ outL, int ldo, int M) {
    extern __shared__ char smem_raw[];
    char* smem = (char*)(((uintptr_t)smem_raw + 1023) & ~(uintptr_t)1023);
    const uint32_t tiles = smem_u32(smem);

    const int tid  = threadIdx.x;
    const int lane = tid & 31, wid = tid >> 5;
    const int m0   = blockIdx.x * 64;

    const int wm = (wid & 1) * 32;       // 2 m-groups of 32 rows
    const int wn = (wid >> 1) * 32;      // 4 n-groups of 32 cols

    float acc[2][4][4];
    #pragma unroll
    for (int i = 0; i < 2; i++)
        #pragma unroll
        for (int j = 0; j < 4; j++)
            #pragma unroll
            for (int q = 0; q < 4; q++) acc[i][j][q] = 0.f;

    const int nk = ct.nk;

    // A ldmatrix lane addressing
    const int r_in = ((lane >> 3) & 1) * 8 + (lane & 7);
    const int ca8  = (lane >> 4) * 8;
    // B ldmatrix x4 (two n8 slices per load)
    const int bg   = lane >> 3;
    const int brow = lane & 7;
    const int b_na_off  = (bg >> 1) * 8;
    const int b_kslice  = (bg & 1) * 8;

    load_tiles(tiles, 0, tid, m0, M, ct.A[0], ct.lda[0], ct.B[0], ct.ldb[0]);
    if (nk > 1) load_tiles(tiles, 1, tid, m0, M, ct.A[1], ct.lda[1], ct.B[1], ct.ldb[1]);

    #pragma unroll 1
    for (int c = 0; c < nk; c++) {
        if (c + 1 < nk) asm volatile("cp.async.wait_group 1;" ::: "memory");
        else            asm volatile("cp.async.wait_group 0;" ::: "memory");
        __syncthreads();
        if (c + 2 < nk) {
            int cn = c + 2;
            load_tiles(tiles, cn % 3, tid, m0, M, ct.A[cn], ct.lda[cn], ct.B[cn], ct.ldb[cn]);
        }

        uint32_t abase = tiles + (uint32_t)(c % 3) * STAGE_SZ;
        uint32_t bbase = abase + 8192u;
        #pragma unroll
        for (int ka = 0; ka < 4; ka++) {
            uint32_t a[2][4];
            #pragma unroll
            for (int ma = 0; ma < 2; ma++) {
                int r = wm + ma * 16 + r_in, cc = ka * 16 + ca8;
                ldm_x4(a[ma], abase + SW128((uint32_t)(r * 128 + cc * 2)));
            }
            uint32_t b[2][4];
            #pragma unroll
            for (int na2 = 0; na2 < 2; na2++) {
                int r  = wn + na2 * 16 + b_na_off + brow;
                int cc = ka * 16 + b_kslice;
                ldm_x4(b[na2], bbase + SW128((uint32_t)(r * 128 + cc * 2)));
            }
            #pragma unroll
            for (int ma = 0; ma < 2; ma++)
                #pragma unroll
                for (int na = 0; na < 4; na++)
                    mma_bf16(acc[ma][na], a[ma], &b[na >> 1][(na & 1) * 2]);
        }
    }
    __syncthreads();

    // park accumulators in smem C [64][132] fp32
    float* C = (float*)smem;
    #pragma unroll
    for (int ma = 0; ma < 2; ma++)
        #pragma unroll
        for (int na = 0; na < 4; na++) {
            int r0 = wm + ma * 16 + (lane >> 2);
            int cc = wn + na * 8 + 2 * (lane & 3);
            C[r0 * 132 + cc]           = acc[ma][na][0];
            C[r0 * 132 + cc + 1]       = acc[ma][na][1];
            C[(r0 + 8) * 132 + cc]     = acc[ma][na][2];
            C[(r0 + 8) * 132 + cc + 1] = acc[ma][na][3];
        }
    __syncthreads();

    // epilogue: warp per row (8 rows per warp)
    #pragma unroll 1
    for (int t = 0; t < 8; t++) {
        int rr  = wid + t * 8;
        int row = m0 + rr;
        if (row >= M) continue;
        float4 v = *reinterpret_cast<float4*>(C + rr * 132 + lane * 4);
        float4 bb = *reinterpret_cast<const float4*>(bias + lane * 4);
        v.x += bb.x; v.y += bb.y; v.z += bb.z; v.w += bb.w;
        if (MODE == 2) {
            float s  = v.x + v.y + v.z + v.w;
            float ss = v.x * v.x + v.y * v.y + v.z * v.z + v.w * v.w;
            #pragma unroll
            for (int off = 16; off; off >>= 1) {
                s  += __shfl_xor_sync(0xffffffffu, s,  off);
                ss += __shfl_xor_sync(0xffffffffu, ss, off);
            }
            float mu  = s * (1.0f / 128.0f);
            float var = ss * (1.0f / 128.0f) - mu * mu;
            float inv = rsqrtf(var + 1e-5f);
            float4 gg = *reinterpret_cast<const float4*>(lng + lane * 4);
            float4 ob = *reinterpret_cast<const float4*>(lnb + lane * 4);
            v.x = (v.x - mu) * inv * gg.x + ob.x;
            v.y = (v.y - mu) * inv * gg.y + ob.y;
            v.z = (v.z - mu) * inv * gg.z + ob.z;
            v.w = (v.w - mu) * inv * gg.w + ob.w;
            if (skip) {
                float4 sk = *reinterpret_cast<const float4*>(skip + (size_t)row * LD + lane * 4);
                v.x += sk.x; v.y += sk.y; v.z += sk.z; v.w += sk.w;
            }
        }
        if (MODE != 0) {
            v.x = fmaxf(v.x, 0.f); v.y = fmaxf(v.y, 0.f);
            v.z = fmaxf(v.z, 0.f); v.w = fmaxf(v.w, 0.f);
        }
        if (outF) {
            *reinterpret_cast<float4*>(outF + (size_t)row * ldF + lane * 4) = v;
        }
        if (MODE != 0) {
            union { __nv_bfloat16 h[4]; uint2 u; } ph, pl;
            float vv[4] = {v.x, v.y, v.z, v.w};
            #pragma unroll
            for (int jj = 0; jj < 4; jj++) split2(vv[jj], ph.h[jj], pl.h[jj]);
            *reinterpret_cast<uint2*>(outH + (size_t)row * ldo + lane * 4) = ph.u;
            *reinterpret_cast<uint2*>(outL + (size_t)row * ldo + lane * 4) = pl.u;
        }
    }
}

// host-side chunk table builder: append one segment (nch chunks of K=64)
static inline void add_seg(ChunkTab& ct, const __nv_bfloat16* A, int lda,
                           const __nv_bfloat16* B, int ldb, int nch) {
    for (int c = 0; c < nch; c++) {
        ct.A[ct.nk]   = A + c * 64;
        ct.B[ct.nk]   = B + c * 64;
        ct.lda[ct.nk] = lda;
        ct.ldb[ct.nk] = ldb;
        ct.nk++;
    }
}

// ---------------- launch ----------------
extern "C" void kernel_launch(void* const* d_in, const int* in_sizes, int n_in,
                              void* d_out, int out_size) {
    const float* x       = (const float*)d_in[0];
    const int*   ei      = (const int*)  d_in[1];
    const float* emb_W   = (const float*)d_in[2];
    const float* emb_b   = (const float*)d_in[3];
    const float* lin_l_W = (const float*)d_in[4];
    const float* lin_l_b = (const float*)d_in[5];
    const float* lin_r_W = (const float*)d_in[6];
    const float* ln_g    = (const float*)d_in[7];
    const float* ln_b    = (const float*)d_in[8];
    const float* fus_W1  = (const float*)d_in[9];
    const float* fus_b1  = (const float*)d_in[10];
    const float* fus_W2  = (const float*)d_in[11];
    const float* fus_b2  = (const float*)d_in[12];
    float* out = (float*)d_out;

    const int M = in_sizes[0] / INDIM;
    const int E = in_sizes[1] / 2;

    float *REPS; __nv_bfloat16 *RH, *RL, *XH, *XL, *AGGH, *AGGL, *TMPH, *TMPL, *W;
    int *CNT;
    cudaGetSymbolAddress((void**)&REPS, g_REPS);
    cudaGetSymbolAddress((void**)&RH,   g_RH);
    cudaGetSymbolAddress((void**)&RL,   g_RL);
    cudaGetSymbolAddress((void**)&XH,   g_XH);
    cudaGetSymbolAddress((void**)&XL,   g_XL);
    cudaGetSymbolAddress((void**)&AGGH, g_AGGH);
    cudaGetSymbolAddress((void**)&AGGL, g_AGGL);
    cudaGetSymbolAddress((void**)&TMPH, g_TMPH);
    cudaGetSymbolAddress((void**)&TMPL, g_TMPL);
    cudaGetSymbolAddress((void**)&W,    g_W);
    cudaGetSymbolAddress((void**)&CNT,  g_cnt);

    cudaFuncSetAttribute(k_mgemm<0>, cudaFuncAttributeMaxDynamicSharedMemorySize, DSMEM);
    cudaFuncSetAttribute(k_mgemm<1>, cudaFuncAttributeMaxDynamicSharedMemorySize, DSMEM);
    cudaFuncSetAttribute(k_mgemm<2>, cudaFuncAttributeMaxDynamicSharedMemorySize, DSMEM);

    const int* src = ei;
    const int* dst = ei + E;

    const int G = (M + 63) / 64;
    const int warp_grid = (M + 7) / 8;

    // ---- prep + CSR ----
    cudaMemsetAsync(CNT, 0, (size_t)M * sizeof(int), 0);
    k_wsplit_all<<<(270336 + 255) / 256, 256>>>(emb_W, lin_l_W, lin_r_W, fus_W1, fus_W2);
    k_count<<<(E + 255) / 256, 256>>>(dst, E);
    k_xsplit<<<((M * 80) + 255) / 256, 256>>>(x, M);

    // ---- embedding: relu(x@W+b) -> RH/RL slice0 ----
    {
        ChunkTab ct; ct.nk = 0;
        add_seg(ct, XH, KX, W + W_EMB_HI, KX, 5);
        add_seg(ct, XH, KX, W + W_EMB_LO, KX, 5);
        add_seg(ct, XL, KX, W + W_EMB_HI, KX, 5);
        k_mgemm<1><<<G, 256, DSMEM>>>(ct, emb_b, nullptr, nullptr, nullptr,
                                      nullptr, 0, RH, RL, LD, M);
    }

    k_scan<<<1, 1024>>>(M);
    k_fill<<<(E + 255) / 256, 256>>>(src, dst, E);

    // ---- layers ----
    for (int i = 0; i < NL; i++) {
        k_agg<<<warp_grid, 256>>>(RH + (size_t)i * HID, M);
        ChunkTab ct; ct.nk = 0;
        const __nv_bfloat16* LLH = W + W_LINL(i);
        const __nv_bfloat16* LLL = LLH + 16384;
        const __nv_bfloat16* LRH = W + W_LINR(i);
        const __nv_bfloat16* LRL = LRH + 16384;
        const __nv_bfloat16* HHi = RH + (size_t)i * HID;
        const __nv_bfloat16* HLo = RL + (size_t)i * HID;
        add_seg(ct, AGGH, HID, LLH, HID, 2);
        add_seg(ct, AGGH, HID, LLL, HID, 2);
        add_seg(ct, AGGL, HID, LLH, HID, 2);
        add_seg(ct, HHi,  LD,  LRH, HID, 2);
        add_seg(ct, HHi,  LD,  LRL, HID, 2);
        add_seg(ct, HLo,  LD,  LRH, HID, 2);
        k_mgemm<2><<<G, 256, DSMEM>>>(ct, lin_l_b + (size_t)i * HID,
                                      ln_g + (size_t)i * HID, ln_b + (size_t)i * HID,
                                      (i > 0) ? (REPS + (size_t)i * HID) : nullptr,
                                      (i + 1 < NL) ? (REPS + (size_t)(i + 1) * HID) : nullptr, LD,
                                      RH + (size_t)(i + 1) * HID, RL + (size_t)(i + 1) * HID, LD, M);
    }

    // ---- fusion MLP ----
    {
        ChunkTab ct; ct.nk = 0;
        add_seg(ct, RH, LD, W + W_FUS1_HI, LD, 10);
        add_seg(ct, RH, LD, W + W_FUS1_LO, LD, 10);
        add_seg(ct, RL, LD, W + W_FUS1_HI, LD, 10);
        k_mgemm<1><<<G, 256, DSMEM>>>(ct, fus_b1, nullptr, nullptr, nullptr,
                                      nullptr, 0, TMPH, TMPL, HID, M);
    }
    {
        ChunkTab ct; ct.nk = 0;
        add_seg(ct, TMPH, HID, W + W_FUS2_HI, HID, 2);
        add_seg(ct, TMPH, HID, W + W_FUS2_LO, HID, 2);
        add_seg(ct, TMPL, HID, W + W_FUS2_HI, HID, 2);
        k_mgemm<0><<<G, 256, DSMEM>>>(ct, fus_b2, nullptr, nullptr, nullptr,
                                      out, HID, nullptr, nullptr, 0, M);
    }
}

// round 12
// speedup vs baseline: 1.5530x; 1.2208x over previous
#include <cuda_runtime.h>
#include <cuda_fp16.h>
#include <cstdint>
#include <math.h>

#define NN    50000
#define EE    800000
#define INDIM 300
#define HID   128
#define NL    4
#define LD    640        // (NL+1)*HID reps row
#define KX    320        // padded x width

// weight pack offsets (elements) — fp16 hi/lo arrays per matrix, [128][Kp] row-major
#define W_EMB_HI 0
#define W_EMB_LO 40960
#define W_LINL(i) (81920  + (i) * 32768)   // lo at +16384
#define W_LINR(i) (212992 + (i) * 32768)   // lo at +16384
#define W_FUS1_HI 344064
#define W_FUS1_LO 425984
#define W_FUS2_HI 507904
#define W_FUS2_LO 524288
#define W_TOTAL   540672

// BM=64, BN=128: stage = A(8KB) + B(16KB) = 24KB, 3 stages = 72KB
#define STAGE_SZ 24576
#define DSMEM (1024 + 3 * STAGE_SZ)
#define MAXCH 20

// ---------------- scratch ----------------
__device__ __align__(256) float   g_REPS[(size_t)NN * LD];   // fp32 skip slices 1..3
__device__ __align__(256) __half  g_RF  [(size_t)NN * LD];   // fp16 activations (agg + GEMM A)
__device__ __align__(256) __half  g_XF  [(size_t)NN * KX];
__device__ __align__(256) __half  g_AGGF[(size_t)NN * HID];
__device__ __align__(256) __half  g_TMPF[(size_t)NN * HID];
__device__ __align__(256) __half  g_W   [W_TOTAL];
__device__ float g_invdeg[NN];
__device__ int   g_cnt[NN];
__device__ int   g_cursor[NN];
__device__ int   g_rowptr[NN + 1];
__device__ int   g_col[EE];

// per-chunk pointer table, built on host, passed by value (constant bank)
struct ChunkTab {
    const __half* A[MAXCH];   // pre-offset by k0
    const __half* B[MAXCH];   // pre-offset by k0
    int lda[MAXCH];
    int ldb[MAXCH];
    int nk;
};

// ---------------- helpers ----------------
__device__ __forceinline__ uint32_t smem_u32(const void* p) {
    uint32_t a;
    asm("{ .reg .u64 t; cvta.to.shared.u64 t, %1; cvt.u32.u64 %0, t; }" : "=r"(a) : "l"(p));
    return a;
}
#define SW128(b) ((b) ^ (((b) >> 3) & 0x70))

__device__ __forceinline__ void cp16(uint32_t dst, const void* src, int sz) {
    asm volatile("cp.async.cg.shared.global [%0], [%1], 16, %2;"
                 :: "r"(dst), "l"(src), "r"(sz) : "memory");
}
__device__ __forceinline__ void ldm_x4(uint32_t* r, uint32_t addr) {
    asm volatile("ldmatrix.sync.aligned.m8n8.x4.shared.b16 {%0,%1,%2,%3}, [%4];"
                 : "=r"(r[0]), "=r"(r[1]), "=r"(r[2]), "=r"(r[3]) : "r"(addr));
}
__device__ __forceinline__ void mma_f16(float* c, const uint32_t* a, const uint32_t* b) {
    asm volatile(
        "mma.sync.aligned.m16n8k16.row.col.f32.f16.f16.f32 "
        "{%0,%1,%2,%3}, {%4,%5,%6,%7}, {%8,%9}, {%0,%1,%2,%3};"
        : "+f"(c[0]), "+f"(c[1]), "+f"(c[2]), "+f"(c[3])
        : "r"(a[0]), "r"(a[1]), "r"(a[2]), "r"(a[3]), "r"(b[0]), "r"(b[1]));
}
__device__ __forceinline__ void split2h(float v, __half& hi, __half& lo) {
    hi = __float2half(v);
    lo = __float2half(v - __half2float(hi));
}

// ---------------- CSR build ----------------
__global__ void k_count(const int* __restrict__ dst, int E) {
    int i = blockIdx.x * blockDim.x + threadIdx.x;
    if (i < E) atomicAdd(&g_cnt[dst[i]], 1);
}

__global__ void __launch_bounds__(1024) k_scan(int M) {
    const int T = 1024;
    int t = threadIdx.x;
    int per = (M + T - 1) / T;
    int beg = t * per;
    int end = min(beg + per, M);
    int sum = 0;
    for (int i = beg; i < end; i++) sum += g_cnt[i];

    int lane = t & 31, wid = t >> 5;
    int v = sum;
    #pragma unroll
    for (int o = 1; o < 32; o <<= 1) {
        int u = __shfl_up_sync(0xffffffffu, v, o);
        if (lane >= o) v += u;
    }
    __shared__ int ws[32];
    if (lane == 31) ws[wid] = v;
    __syncthreads();
    if (wid == 0) {
        int wv = ws[lane];
        #pragma unroll
        for (int o = 1; o < 32; o <<= 1) {
            int u = __shfl_up_sync(0xffffffffu, wv, o);
            if (lane >= o) wv += u;
        }
        ws[lane] = wv;
    }
    __syncthreads();
    int run = v - sum + (wid ? ws[wid - 1] : 0);
    for (int i = beg; i < end; i++) {
        int c = g_cnt[i];
        g_rowptr[i] = run;
        g_cursor[i] = run;
        g_invdeg[i] = 1.0f / fmaxf((float)c, 1.0f);
        run += c;
    }
    if (t == T - 1) g_rowptr[M] = run;
}

__global__ void k_fill(const int* __restrict__ src, const int* __restrict__ dst, int E) {
    int i = blockIdx.x * blockDim.x + threadIdx.x;
    if (i < E) {
        int pos = atomicAdd(&g_cursor[dst[i]], 1);
        g_col[pos] = src[i];
    }
}

// ---------------- weight prep (one launch; writes fp16 hi+lo arrays) ----------------
__device__ __forceinline__ void wsplit_one(const float* W, __half* ohi,
                                           __half* olo, int idx, int K, int Kp) {
    int n = idx / Kp, kp = idx % Kp;
    __half hi, lo;
    if (kp < K) {
        split2h(W[(size_t)kp * 128 + n], hi, lo);
    } else {
        hi = __float2half(0.f); lo = hi;
    }
    ohi[(size_t)n * Kp + kp] = hi;
    olo[(size_t)n * Kp + kp] = lo;
}

__global__ void k_wsplit_all(const float* __restrict__ emb_W,
                             const float* __restrict__ lin_l_W,
                             const float* __restrict__ lin_r_W,
                             const float* __restrict__ fus_W1,
                             const float* __restrict__ fus_W2) {
    int w = blockIdx.x * blockDim.x + threadIdx.x;
    if (w < 40960) {
        wsplit_one(emb_W, g_W + W_EMB_HI, g_W + W_EMB_LO, w, 300, 320);
    } else if (w < 106496) {
        int u = w - 40960, i = u >> 14;
        wsplit_one(lin_l_W + (size_t)i * 16384, g_W + W_LINL(i), g_W + W_LINL(i) + 16384,
                   u & 16383, 128, 128);
    } else if (w < 172032) {
        int u = w - 106496, i = u >> 14;
        wsplit_one(lin_r_W + (size_t)i * 16384, g_W + W_LINR(i), g_W + W_LINR(i) + 16384,
                   u & 16383, 128, 128);
    } else if (w < 253952) {
        wsplit_one(fus_W1, g_W + W_FUS1_HI, g_W + W_FUS1_LO, w - 172032, 640, 640);
    } else if (w < 270336) {
        wsplit_one(fus_W2, g_W + W_FUS2_HI, g_W + W_FUS2_LO, w - 253952, 128, 128);
    }
}

// x [M,300] fp32 -> XF [M,320] fp16, zero pad
__global__ void k_xcvt(const float* __restrict__ x, int M) {
    int idx = blockIdx.x * blockDim.x + threadIdx.x;
    int row = idx / 80, g = idx % 80;
    if (row >= M) return;
    float vv[4] = {0.f, 0.f, 0.f, 0.f};
    if (g < 75) {
        float4 t = *reinterpret_cast<const float4*>(x + (size_t)row * INDIM + g * 4);
        vv[0] = t.x; vv[1] = t.y; vv[2] = t.z; vv[3] = t.w;
    }
    union { __half h[4]; uint2 u; } p;
    #pragma unroll
    for (int j = 0; j < 4; j++) p.h[j] = __float2half(vv[j]);
    *reinterpret_cast<uint2*>(g_XF + (size_t)row * KX + g * 4) = p.u;
}

// ---------------- mean aggregation from fp16 rows -> fp16 ----------------
__global__ void k_agg(const __half* __restrict__ H /* RF slice, ld=LD */, int M) {
    int gw   = (blockIdx.x * blockDim.x + threadIdx.x) >> 5;
    int lane = threadIdx.x & 31;
    if (gw >= M) return;
    int beg = g_rowptr[gw], end = g_rowptr[gw + 1];
    float a0 = 0.f, a1 = 0.f, a2 = 0.f, a3 = 0.f;
    float b0 = 0.f, b1 = 0.f, b2 = 0.f, b3 = 0.f;
    union U { uint2 u; __half2 h2[2]; };
    for (int base = beg; base < end; base += 32) {
        int idx = (base + lane < end) ? g_col[base + lane] : 0;
        int cnt = min(32, end - base);
        int j = 0;
        for (; j + 3 < cnt; j += 4) {
            int s0 = __shfl_sync(0xffffffffu, idx, j);
            int s1 = __shfl_sync(0xffffffffu, idx, j + 1);
            int s2 = __shfl_sync(0xffffffffu, idx, j + 2);
            int s3 = __shfl_sync(0xffffffffu, idx, j + 3);
            U u0, u1, u2, u3;
            u0.u = *reinterpret_cast<const uint2*>(H + (size_t)s0 * LD + lane * 4);
            u1.u = *reinterpret_cast<const uint2*>(H + (size_t)s1 * LD + lane * 4);
            u2.u = *reinterpret_cast<const uint2*>(H + (size_t)s2 * LD + lane * 4);
            u3.u = *reinterpret_cast<const uint2*>(H + (size_t)s3 * LD + lane * 4);
            float2 p;
            p = __half22float2(u0.h2[0]); a0 += p.x; a1 += p.y;
            p = __half22float2(u0.h2[1]); a2 += p.x; a3 += p.y;
            p = __half22float2(u1.h2[0]); b0 += p.x; b1 += p.y;
            p = __half22float2(u1.h2[1]); b2 += p.x; b3 += p.y;
            p = __half22float2(u2.h2[0]); a0 += p.x; a1 += p.y;
            p = __half22float2(u2.h2[1]); a2 += p.x; a3 += p.y;
            p = __half22float2(u3.h2[0]); b0 += p.x; b1 += p.y;
            p = __half22float2(u3.h2[1]); b2 += p.x; b3 += p.y;
        }
        for (; j < cnt; j++) {
            int s = __shfl_sync(0xffffffffu, idx, j);
            U u; u.u = *reinterpret_cast<const uint2*>(H + (size_t)s * LD + lane * 4);
            float2 p;
            p = __half22float2(u.h2[0]); a0 += p.x; a1 += p.y;
            p = __half22float2(u.h2[1]); a2 += p.x; a3 += p.y;
        }
    }
    a0 += b0; a1 += b1; a2 += b2; a3 += b3;
    float w = g_invdeg[gw];
    union { __half h[4]; uint2 u; } p;
    p.h[0] = __float2half(a0 * w);
    p.h[1] = __float2half(a1 * w);
    p.h[2] = __float2half(a2 * w);
    p.h[3] = __float2half(a3 * w);
    *reinterpret_cast<uint2*>(g_AGGF + (size_t)gw * HID + lane * 4) = p.u;
}

// ---------------- tile loader: A 64x64fp16 (8KB), B 128x64fp16 (16KB) ----------------
__device__ __forceinline__ void load_tiles(uint32_t tiles, int s, int tid, int m0, int M,
                                           const __half* A, int lda,
                                           const __half* B, int ldb) {
    uint32_t abase = tiles + (uint32_t)s * STAGE_SZ;
    uint32_t bbase = abase + 8192u;
    #pragma unroll
    for (int i = 0; i < 2; i++) {
        int v = tid + i * 256;
        int r = v >> 3, ch = v & 7;
        uint32_t bo = (uint32_t)(r * 128 + ch * 16);
        int row = m0 + r;
        int rc = row < M ? row : 0;
        cp16(abase + SW128(bo), A + (rc * lda + ch * 8), row < M ? 16 : 0);
    }
    #pragma unroll
    for (int i = 0; i < 4; i++) {
        int v = tid + i * 256;
        int r = v >> 3, ch = v & 7;
        uint32_t bo = (uint32_t)(r * 128 + ch * 16);
        cp16(bbase + SW128(bo), B + (r * ldb + ch * 8), 16);
    }
    asm volatile("cp.async.commit_group;" ::: "memory");
}

// ---------------- mma.sync GEMM, 64x128 tile, BK=64, 3-stage, chunk table ----------------
// MODE 0: C + bias                              -> outF
// MODE 1: relu(C + bias)                        -> [outF] + out16
// MODE 2: LN(C + bias)*g+b (+skip), relu        -> [outF] + out16
template <int MODE>
__global__ void __launch_bounds__(256, 3)
k_mgemm(ChunkTab ct,
        const float* __restrict__ bias, const float* __restrict__ lng, const float* __restrict__ lnb,
        const float* __restrict__ skip, float* __restrict__ outF, int ldF,
        __half* __restrict__ out16, int ldo, int M) {
    extern __shared__ char smem_raw[];
    char* smem = (char*)(((uintptr_t)smem_raw + 1023) & ~(uintptr_t)1023);
    const uint32_t tiles = smem_u32(smem);

    const int tid  = threadIdx.x;
    const int lane = tid & 31, wid = tid >> 5;
    const int m0   = blockIdx.x * 64;

    const int wm = (wid & 1) * 32;
    const int wn = (wid >> 1) * 32;

    float acc[2][4][4];
    #pragma unroll
    for (int i = 0; i < 2; i++)
        #pragma unroll
        for (int j = 0; j < 4; j++)
            #pragma unroll
            for (int q = 0; q < 4; q++) acc[i][j][q] = 0.f;

    const int nk = ct.nk;

    const int r_in = ((lane >> 3) & 1) * 8 + (lane & 7);
    const int ca8  = (lane >> 4) * 8;
    const int bg   = lane >> 3;
    const int brow = lane & 7;
    const int b_na_off  = (bg >> 1) * 8;
    const int b_kslice  = (bg & 1) * 8;

    load_tiles(tiles, 0, tid, m0, M, ct.A[0], ct.lda[0], ct.B[0], ct.ldb[0]);
    if (nk > 1) load_tiles(tiles, 1, tid, m0, M, ct.A[1], ct.lda[1], ct.B[1], ct.ldb[1]);

    #pragma unroll 1
    for (int c = 0; c < nk; c++) {
        if (c + 1 < nk) asm volatile("cp.async.wait_group 1;" ::: "memory");
        else            asm volatile("cp.async.wait_group 0;" ::: "memory");
        __syncthreads();
        if (c + 2 < nk) {
            int cn = c + 2;
            load_tiles(tiles, cn % 3, tid, m0, M, ct.A[cn], ct.lda[cn], ct.B[cn], ct.ldb[cn]);
        }

        uint32_t abase = tiles + (uint32_t)(c % 3) * STAGE_SZ;
        uint32_t bbase = abase + 8192u;
        #pragma unroll
        for (int ka = 0; ka < 4; ka++) {
            uint32_t a[2][4];
            #pragma unroll
            for (int ma = 0; ma < 2; ma++) {
                int r = wm + ma * 16 + r_in, cc = ka * 16 + ca8;
                ldm_x4(a[ma], abase + SW128((uint32_t)(r * 128 + cc * 2)));
            }
            uint32_t b[2][4];
            #pragma unroll
            for (int na2 = 0; na2 < 2; na2++) {
                int r  = wn + na2 * 16 + b_na_off + brow;
                int cc = ka * 16 + b_kslice;
                ldm_x4(b[na2], bbase + SW128((uint32_t)(r * 128 + cc * 2)));
            }
            #pragma unroll
            for (int ma = 0; ma < 2; ma++)
                #pragma unroll
                for (int na = 0; na < 4; na++)
                    mma_f16(acc[ma][na], a[ma], &b[na >> 1][(na & 1) * 2]);
        }
    }
    __syncthreads();

    // park accumulators in smem C [64][132] fp32
    float* C = (float*)smem;
    #pragma unroll
    for (int ma = 0; ma < 2; ma++)
        #pragma unroll
        for (int na = 0; na < 4; na++) {
            int r0 = wm + ma * 16 + (lane >> 2);
            int cc = wn + na * 8 + 2 * (lane & 3);
            C[r0 * 132 + cc]           = acc[ma][na][0];
            C[r0 * 132 + cc + 1]       = acc[ma][na][1];
            C[(r0 + 8) * 132 + cc]     = acc[ma][na][2];
            C[(r0 + 8) * 132 + cc + 1] = acc[ma][na][3];
        }
    __syncthreads();

    // epilogue: warp per row (8 rows per warp)
    #pragma unroll 1
    for (int t = 0; t < 8; t++) {
        int rr  = wid + t * 8;
        int row = m0 + rr;
        if (row >= M) continue;
        float4 v = *reinterpret_cast<float4*>(C + rr * 132 + lane * 4);
        float4 bb = *reinterpret_cast<const float4*>(bias + lane * 4);
        v.x += bb.x; v.y += bb.y; v.z += bb.z; v.w += bb.w;
        if (MODE == 2) {
            float s  = v.x + v.y + v.z + v.w;
            float ss = v.x * v.x + v.y * v.y + v.z * v.z + v.w * v.w;
            #pragma unroll
            for (int off = 16; off; off >>= 1) {
                s  += __shfl_xor_sync(0xffffffffu, s,  off);
                ss += __shfl_xor_sync(0xffffffffu, ss, off);
            }
            float mu  = s * (1.0f / 128.0f);
            float var = ss * (1.0f / 128.0f) - mu * mu;
            float inv = rsqrtf(var + 1e-5f);
            float4 gg = *reinterpret_cast<const float4*>(lng + lane * 4);
            float4 ob = *reinterpret_cast<const float4*>(lnb + lane * 4);
            v.x = (v.x - mu) * inv * gg.x + ob.x;
            v.y = (v.y - mu) * inv * gg.y + ob.y;
            v.z = (v.z - mu) * inv * gg.z + ob.z;
            v.w = (v.w - mu) * inv * gg.w + ob.w;
            if (skip) {
                float4 sk = *reinterpret_cast<const float4*>(skip + (size_t)row * LD + lane * 4);
                v.x += sk.x; v.y += sk.y; v.z += sk.z; v.w += sk.w;
            }
        }
        if (MODE != 0) {
            v.x = fmaxf(v.x, 0.f); v.y = fmaxf(v.y, 0.f);
            v.z = fmaxf(v.z, 0.f); v.w = fmaxf(v.w, 0.f);
        }
        if (outF) {
            *reinterpret_cast<float4*>(outF + (size_t)row * ldF + lane * 4) = v;
        }
        if (MODE != 0) {
            union { __half h[4]; uint2 u; } p;
            p.h[0] = __float2half(v.x);
            p.h[1] = __float2half(v.y);
            p.h[2] = __float2half(v.z);
            p.h[3] = __float2half(v.w);
            *reinterpret_cast<uint2*>(out16 + (size_t)row * ldo + lane * 4) = p.u;
        }
    }
}

// host-side chunk table builder
static inline void add_seg(ChunkTab& ct, const __half* A, int lda,
                           const __half* B, int ldb, int nch) {
    for (int c = 0; c < nch; c++) {
        ct.A[ct.nk]   = A + c * 64;
        ct.B[ct.nk]   = B + c * 64;
        ct.lda[ct.nk] = lda;
        ct.ldb[ct.nk] = ldb;
        ct.nk++;
    }
}

// ---------------- launch ----------------
extern "C" void kernel_launch(void* const* d_in, const int* in_sizes, int n_in,
                              void* d_out, int out_size) {
    const float* x       = (const float*)d_in[0];
    const int*   ei      = (const int*)  d_in[1];
    const float* emb_W   = (const float*)d_in[2];
    const float* emb_b   = (const float*)d_in[3];
    const float* lin_l_W = (const float*)d_in[4];
    const float* lin_l_b = (const float*)d_in[5];
    const float* lin_r_W = (const float*)d_in[6];
    const float* ln_g    = (const float*)d_in[7];
    const float* ln_b    = (const float*)d_in[8];
    const float* fus_W1  = (const float*)d_in[9];
    const float* fus_b1  = (const float*)d_in[10];
    const float* fus_W2  = (const float*)d_in[11];
    const float* fus_b2  = (const float*)d_in[12];
    float* out = (float*)d_out;

    const int M = in_sizes[0] / INDIM;
    const int E = in_sizes[1] / 2;

    float *REPS; __half *RF, *XF, *AGGF, *TMPF, *W;
    int *CNT;
    cudaGetSymbolAddress((void**)&REPS, g_REPS);
    cudaGetSymbolAddress((void**)&RF,   g_RF);
    cudaGetSymbolAddress((void**)&XF,   g_XF);
    cudaGetSymbolAddress((void**)&AGGF, g_AGGF);
    cudaGetSymbolAddress((void**)&TMPF, g_TMPF);
    cudaGetSymbolAddress((void**)&W,    g_W);
    cudaGetSymbolAddress((void**)&CNT,  g_cnt);

    cudaFuncSetAttribute(k_mgemm<0>, cudaFuncAttributeMaxDynamicSharedMemorySize, DSMEM);
    cudaFuncSetAttribute(k_mgemm<1>, cudaFuncAttributeMaxDynamicSharedMemorySize, DSMEM);
    cudaFuncSetAttribute(k_mgemm<2>, cudaFuncAttributeMaxDynamicSharedMemorySize, DSMEM);

    const int* src = ei;
    const int* dst = ei + E;

    const int G = (M + 63) / 64;
    const int warp_grid = (M + 7) / 8;

    // ---- prep + CSR ----
    cudaMemsetAsync(CNT, 0, (size_t)M * sizeof(int), 0);
    k_wsplit_all<<<(270336 + 255) / 256, 256>>>(emb_W, lin_l_W, lin_r_W, fus_W1, fus_W2);
    k_count<<<(E + 255) / 256, 256>>>(dst, E);
    k_xcvt<<<((M * 80) + 255) / 256, 256>>>(x, M);

    // ---- embedding: relu(x@W+b) -> RF slice0 ----
    {
        ChunkTab ct; ct.nk = 0;
        add_seg(ct, XF, KX, W + W_EMB_HI, KX, 5);
        add_seg(ct, XF, KX, W + W_EMB_LO, KX, 5);
        k_mgemm<1><<<G, 256, DSMEM>>>(ct, emb_b, nullptr, nullptr, nullptr,
                                      nullptr, 0, RF, LD, M);
    }

    k_scan<<<1, 1024>>>(M);
    k_fill<<<(E + 255) / 256, 256>>>(src, dst, E);

    // ---- layers ----
    for (int i = 0; i < NL; i++) {
        k_agg<<<warp_grid, 256>>>(RF + (size_t)i * HID, M);
        ChunkTab ct; ct.nk = 0;
        const __half* LLH = W + W_LINL(i);
        const __half* LLL = LLH + 16384;
        const __half* LRH = W + W_LINR(i);
        const __half* LRL = LRH + 16384;
        const __half* HF  = RF + (size_t)i * HID;
        add_seg(ct, AGGF, HID, LLH, HID, 2);
        add_seg(ct, AGGF, HID, LLL, HID, 2);
        add_seg(ct, HF,   LD,  LRH, HID, 2);
        add_seg(ct, HF,   LD,  LRL, HID, 2);
        k_mgemm<2><<<G, 256, DSMEM>>>(ct, lin_l_b + (size_t)i * HID,
                                      ln_g + (size_t)i * HID, ln_b + (size_t)i * HID,
                                      (i > 0) ? (REPS + (size_t)i * HID) : nullptr,
                                      (i + 1 < NL) ? (REPS + (size_t)(i + 1) * HID) : nullptr, LD,
                                      RF + (size_t)(i + 1) * HID, LD, M);
    }

    // ---- fusion MLP ----
    {
        ChunkTab ct; ct.nk = 0;
        add_seg(ct, RF, LD, W + W_FUS1_HI, LD, 10);
        add_seg(ct, RF, LD, W + W_FUS1_LO, LD, 10);
        k_mgemm<1><<<G, 256, DSMEM>>>(ct, fus_b1, nullptr, nullptr, nullptr,
                                      nullptr, 0, TMPF, HID, M);
    }
    {
        ChunkTab ct; ct.nk = 0;
        add_seg(ct, TMPF, HID, W + W_FUS2_HI, HID, 2);
        add_seg(ct, TMPF, HID, W + W_FUS2_LO, HID, 2);
        k_mgemm<0><<<G, 256, DSMEM>>>(ct, fus_b2, nullptr, nullptr, nullptr,
                                      out, HID, nullptr, 0, M);
    }
}